// round 6
// baseline (speedup 1.0000x reference)
#include <cuda_runtime.h>
#include <math.h>

// ---------------------------------------------------------------------------
// HardConstrainedMLP. proj_pinv(s) = s @ P + Q.
// Solver: 1024 threads/CTA, k-split: half h = t>>9 computes partial dot over
// its k-range (h=0: k 0..251, h=1: k 252..499; split at 252 keeps 16B align).
// Thread owns ONE column c = t&511 of 8 batch rows. P k-pair interleaved:
//   g_P[kp*1024 + 2c + parity] = P[2kp+parity][c]
// P is read once per CTA per iter (halves read disjoint k). Upper half's
// partials are exchanged through the S smem region (fully read by then).
// ---------------------------------------------------------------------------

#define BATCH       1024
#define MDIM        250
#define DTOT        500
#define HDIM        512
#define NITER       1000
#define NCHUNK      4
#define CHUNK       (NITER / NCHUNK)
#define ROWS_PER_CTA 8
#define SOLVER_CTAS (BATCH / ROWS_PER_CTA)
#define NTHR        1024
#define NSLOT       44                 // cached k-pairs in smem (22 per half)

#define OMEGA_F 1.8f
#define ALPHA_F (1.0f / 1.2f)

typedef unsigned long long ull;

#define FFMA2(d, a, b) \
    asm("fma.rn.f32x2 %0, %1, %2, %0;" : "+l"(d) : "l"(a), "l"(b))

__device__ __forceinline__ float2 f32x2_unpack(ull v) {
    float2 r;
    asm("mov.b64 {%0, %1}, %2;" : "=f"(r.x), "=f"(r.y) : "l"(v));
    return r;
}

// Scratch (device globals; zero-initialized, no runtime allocation)
__device__ float g_X1 [BATCH * HDIM];
__device__ float g_X2 [BATCH * HDIM];
__device__ float g_Ys [BATCH * DTOT];
__device__ float g_Q  [BATCH * DTOT];
__device__ float g_S  [BATCH * DTOT];
__device__ float g_P  [250 * 1024];

// ---------------------------------------------------------------------------
// Precompute GEMM (unchanged).
// ---------------------------------------------------------------------------
__device__ void gemm_dev(const float* __restrict__ A, const float* __restrict__ A2,
                         const float* __restrict__ B, const float* __restrict__ bias,
                         float* __restrict__ C,
                         int M, int N, int K, int mode, int bT, int aT)
{
    __shared__ float As[16][64];
    __shared__ float Bs[16][68];
    const int tid = threadIdx.x;
    const int tx = tid & 15, ty = tid >> 4;
    const int m0 = blockIdx.y * 64, n0 = blockIdx.x * 64;

    float acc[4][4];
    #pragma unroll
    for (int i = 0; i < 4; i++)
        #pragma unroll
        for (int j = 0; j < 4; j++) acc[i][j] = 0.f;

    for (int k0 = 0; k0 < K; k0 += 16) {
        #pragma unroll
        for (int i = 0; i < 4; i++) {
            int idx = tid + i * 256;
            int mr = idx >> 4, kk = idx & 15;
            int mg = m0 + mr, kg = k0 + kk;
            float av = 0.f;
            if (mg < M && kg < K) {
                if (aT)       av = A[(size_t)kg * M + mg];
                else if (A2)  av = (kg < MDIM) ? A[(size_t)mg * MDIM + kg]
                                               : A2[(size_t)mg * MDIM + (kg - MDIM)];
                else          av = A[(size_t)mg * K + kg];
            }
            As[kk][mr] = av;
        }
        #pragma unroll
        for (int i = 0; i < 4; i++) {
            int idx = tid + i * 256;
            if (!bT) {
                int kk = idx >> 6, cg = idx & 63;
                int kgl = k0 + kk, cgl = n0 + cg;
                Bs[kk][cg] = (kgl < K && cgl < N) ? B[(size_t)kgl * N + cgl] : 0.f;
            } else {
                int cg = idx >> 4, kk = idx & 15;
                int kgl = k0 + kk, cgl = n0 + cg;
                Bs[kk][cg] = (kgl < K && cgl < N) ? B[(size_t)cgl * K + kgl] : 0.f;
            }
        }
        __syncthreads();
        #pragma unroll
        for (int kk = 0; kk < 16; kk++) {
            float a[4], bb[4];
            #pragma unroll
            for (int i = 0; i < 4; i++) a[i] = As[kk][ty * 4 + i];
            #pragma unroll
            for (int j = 0; j < 4; j++) bb[j] = Bs[kk][tx * 4 + j];
            #pragma unroll
            for (int i = 0; i < 4; i++)
                #pragma unroll
                for (int j = 0; j < 4; j++) acc[i][j] += a[i] * bb[j];
        }
        __syncthreads();
    }

    #pragma unroll
    for (int i = 0; i < 4; i++) {
        int mg = m0 + ty * 4 + i;
        if (mg >= M) continue;
        #pragma unroll
        for (int j = 0; j < 4; j++) {
            int ng = n0 + tx * 4 + j;
            if (ng >= N) continue;
            float v = acc[i][j];
            if (bias) v += bias[ng];
            if (mode == 1)      v = fmaxf(v, 0.f);
            else if (mode == 2) v *= (1.0f / 6.0f);
            if (mode == 4) {
                v = ((mg == ng) ? 1.f : 0.f) - v;
                C[(size_t)(mg >> 1) * 1024 + ng * 2 + (mg & 1)] = v;
            } else {
                C[(size_t)mg * N + ng] = v;
            }
        }
    }
}

__global__ void gemm_kernel(const float* __restrict__ A, const float* __restrict__ A2,
                            const float* __restrict__ B, const float* __restrict__ bias,
                            float* __restrict__ C,
                            int M, int N, int K, int mode, int bT, int aT)
{
    gemm_dev(A, A2, B, bias, C, M, N, K, mode, bT, aT);
}

__global__ void precompute_fused(const float* b, const float* cin,
                                 const float* W1, const float* b1,
                                 const float* Aaug, const float* Ainv,
                                 float* X1, float* Q, float* P)
{
    int z = blockIdx.z;
    if (z == 0) {
        gemm_dev(b, cin, W1, b1, X1, BATCH, HDIM, DTOT, 1, 0, 0);
    } else if (z == 1) {
        gemm_dev(b, nullptr, Ainv, nullptr, Q, BATCH, DTOT, MDIM, 0, 1, 0);
    } else {
        if (blockIdx.y >= 8) return;
        gemm_dev(Aaug, nullptr, Ainv, nullptr, P, DTOT, DTOT, MDIM, 4, 1, 1);
    }
}

// ---------------------------------------------------------------------------
// Solver. smem floats:
//   Ssm[4000] Qsm[4000] Ysm[4000] part[128] nrm[8] tls[8] pad->12288
//   Pcs[44*1024]     total 57344 f = 229,376 B
// ---------------------------------------------------------------------------
#define SMEM_FLOATS (12288 + NSLOT * 1024)
#define SMEM_BYTES  (SMEM_FLOATS * 4)

__device__ __forceinline__ float soc_elem(float tp, int c, float nu, float tt)
{
    if (c < MDIM) return tp;
    if (nu <= tt) return tp;
    if (nu <= -tt) return 0.f;
    float h = 0.5f * (tt + nu);
    return (c == DTOT - 1) ? h : h * tp / (nu + 1e-12f);
}

// partial z over this half's k-range for column c, rows 0..7
// H=0: cached kp 0..21 (slots 0..21),   streamed kp 22..125  (52 steps)
// H=1: cached kp 126..147 (slots 22..43), streamed kp 148..249 (51 steps)
template <int H>
__device__ __forceinline__ void gemm_half(const float* __restrict__ Ssm,
                                          const float* __restrict__ Pcs,
                                          int c, float* zp)
{
    const int tc2 = 2 * c;
    constexpr int nC    = 11;               // cached steps (2 kp each)
    constexpr int kpC   = H ? 126 : 0;
    constexpr int slot0 = H ? 22  : 0;
    constexpr int nS    = H ? 51  : 52;     // streamed steps (2 kp each)
    constexpr int kpS   = H ? 148 : 22;

    ull acc[8];
    #pragma unroll
    for (int r = 0; r < 8; r++) acc[r] = 0ull;

    // cached phase
    #pragma unroll 1
    for (int st = 0; st < nC; st++) {
        const int sl = slot0 + 2 * st;
        ull p0 = *reinterpret_cast<const ull*>(&Pcs[sl * 1024 + tc2]);
        ull p1 = *reinterpret_cast<const ull*>(&Pcs[sl * 1024 + 1024 + tc2]);
        const float* sb = &Ssm[2 * (kpC + 2 * st)];
        #pragma unroll
        for (int r = 0; r < 8; r++) {
            ulonglong2 sv = *reinterpret_cast<const ulonglong2*>(&sb[r * DTOT]);
            FFMA2(acc[r], sv.x, p0);
            FFMA2(acc[r], sv.y, p1);
        }
    }

    // streamed phase, 4-deep prefetch ring
    ull pf[8];
    #pragma unroll
    for (int j = 0; j < 4; j++) {
        pf[2 * j]     = *reinterpret_cast<const ull*>(&g_P[(kpS + 2 * j) * 1024 + tc2]);
        pf[2 * j + 1] = *reinterpret_cast<const ull*>(&g_P[(kpS + 2 * j + 1) * 1024 + tc2]);
    }
    #pragma unroll 4
    for (int s = 0; s < nS; s++) {
        const int kp = kpS + 2 * s;
        const int sl = (s & 3) * 2;
        ull p0 = pf[sl], p1 = pf[sl + 1];
        if (s + 4 < nS) {
            pf[sl]     = *reinterpret_cast<const ull*>(&g_P[(kp + 8) * 1024 + tc2]);
            pf[sl + 1] = *reinterpret_cast<const ull*>(&g_P[(kp + 9) * 1024 + tc2]);
        }
        const float* sb = &Ssm[2 * kp];
        #pragma unroll
        for (int r = 0; r < 8; r++) {
            ulonglong2 sv = *reinterpret_cast<const ulonglong2*>(&sb[r * DTOT]);
            FFMA2(acc[r], sv.x, p0);
            FFMA2(acc[r], sv.y, p1);
        }
    }

    #pragma unroll
    for (int r = 0; r < 8; r++) {
        float2 u = f32x2_unpack(acc[r]);
        zp[r] = u.x + u.y;
    }
}

__global__ void __launch_bounds__(NTHR, 1) solver_kernel(float* __restrict__ out,
                                                         int start_it, int end_it)
{
    extern __shared__ float sm[];
    float* Ssm  = sm;            // 4000
    float* Qsm  = sm + 4000;     // 4000
    float* Ysm  = sm + 8000;     // 4000
    float* part = sm + 12000;    // 128  [warp 0..15][row]
    float* nrm  = sm + 12128;    // 8
    float* tls  = sm + 12136;    // 8
    float* Pcs  = sm + 12288;    // NSLOT*1024

    const int t = threadIdx.x;
    const int h = t >> 9;        // k-half
    const int c = t & 511;       // column
    const int w = t >> 5, lane = t & 31;
    const int row0 = blockIdx.x * ROWS_PER_CTA;
    const bool act = (c < DTOT);

    // startup: S (zeros or g_S), Q, Ys, P cache
    for (int i = t; i < ROWS_PER_CTA * DTOT; i += NTHR) {
        int r = i / DTOT, cc = i - r * DTOT;
        Ssm[i] = (start_it == 0) ? 0.f : g_S[(row0 + r) * DTOT + cc];
        Qsm[i] = g_Q [(row0 + r) * DTOT + cc];
        Ysm[i] = g_Ys[(row0 + r) * DTOT + cc];
    }
    {
        float4* dst = reinterpret_cast<float4*>(Pcs);
        #pragma unroll 1
        for (int i4 = t; i4 < NSLOT * 256; i4 += NTHR) {
            int slot = i4 >> 8, within = i4 & 255;
            int kp = (slot < 22) ? slot : slot + 104;
            dst[i4] = *reinterpret_cast<const float4*>(&g_P[kp * 1024 + within * 4]);
        }
    }
    __syncthreads();

    float zp[8];
    for (int it = start_it; it < end_it; ++it) {
        // lower half snapshots its own S column before it gets clobbered
        float sold[8];
        if (h == 0 && act) {
            #pragma unroll
            for (int r = 0; r < 8; r++) sold[r] = Ssm[r * DTOT + c];
        }

        if (h == 0) gemm_half<0>(Ssm, Pcs, c, zp);
        else        gemm_half<1>(Ssm, Pcs, c, zp);

        __syncthreads();                               // B1: all S reads done
        if (h == 1 && act) {
            #pragma unroll
            for (int r = 0; r < 8; r++) Ssm[r * DTOT + c] = zp[r];
        }
        __syncthreads();                               // B2: partials visible

        float z[8], tp[8];
        if (h == 0) {
            float val[8];
            const bool in_u = act && (c >= MDIM) && (c != DTOT - 1);
            #pragma unroll
            for (int r = 0; r < 8; r++) {
                if (act) {
                    z[r]  = Qsm[r * DTOT + c] + zp[r] + Ssm[r * DTOT + c];
                    tp[r] = ALPHA_F * (2.f * z[r] - sold[r]) - Ysm[r * DTOT + c];
                    val[r] = in_u ? tp[r] * tp[r] : 0.f;
                } else { z[r] = 0.f; tp[r] = 0.f; val[r] = 0.f; }
            }
            #pragma unroll
            for (int off = 16; off; off >>= 1)
                #pragma unroll
                for (int r = 0; r < 8; r++)
                    val[r] += __shfl_down_sync(0xffffffffu, val[r], off);
            if (lane == 0) {
                #pragma unroll
                for (int r = 0; r < 8; r++) part[w * 8 + r] = val[r];
            }
            if (t == DTOT - 1) {
                #pragma unroll
                for (int r = 0; r < 8; r++) tls[r] = tp[r];
            }
        }
        __syncthreads();                               // B3
        if (w < 8 && lane < 16) {                      // warp w reduces row w
            float s = part[lane * 8 + w];
            #pragma unroll
            for (int off = 8; off; off >>= 1)
                s += __shfl_down_sync(0x0000ffffu, s, off);
            if (lane == 0) nrm[w] = sqrtf(s);
        }
        __syncthreads();                               // B4
        if (h == 0 && act) {
            #pragma unroll
            for (int r = 0; r < 8; r++) {
                float tk = soc_elem(tp[r], c, nrm[r], tls[r]);
                Ssm[r * DTOT + c] = sold[r] + OMEGA_F * (tk - z[r]);
            }
        }
        __syncthreads();                               // B5
    }

    if (end_it == NITER) {
        // final z = proj_pinv(s_K)
        if (h == 0) gemm_half<0>(Ssm, Pcs, c, zp);
        else        gemm_half<1>(Ssm, Pcs, c, zp);
        __syncthreads();
        if (h == 1 && act) {
            #pragma unroll
            for (int r = 0; r < 8; r++) Ssm[r * DTOT + c] = zp[r];
        }
        __syncthreads();
        if (h == 0 && act) {
            #pragma unroll
            for (int r = 0; r < 8; r++)
                out[(row0 + r) * DTOT + c] = Qsm[r * DTOT + c] + zp[r] + Ssm[r * DTOT + c];
        }
    } else {
        for (int i = t; i < ROWS_PER_CTA * DTOT; i += NTHR) {
            int r = i / DTOT, cc = i - r * DTOT;
            g_S[(row0 + r) * DTOT + cc] = Ssm[i];
        }
    }
}

// ---------------------------------------------------------------------------
extern "C" void kernel_launch(void* const* d_in, const int* in_sizes, int n_in,
                              void* d_out, int out_size)
{
    const float* b    = (const float*)d_in[0];
    const float* cin  = (const float*)d_in[1];
    const float* W1   = (const float*)d_in[2];
    const float* b1   = (const float*)d_in[3];
    const float* W2   = (const float*)d_in[4];
    const float* b2   = (const float*)d_in[5];
    const float* W3   = (const float*)d_in[6];
    const float* b3   = (const float*)d_in[7];
    const float* Aaug = (const float*)d_in[8];
    const float* Ainv = (const float*)d_in[9];
    float* out = (float*)d_out;

    float *X1, *X2, *Ys, *Q, *P;
    cudaGetSymbolAddress((void**)&X1, g_X1);
    cudaGetSymbolAddress((void**)&X2, g_X2);
    cudaGetSymbolAddress((void**)&Ys, g_Ys);
    cudaGetSymbolAddress((void**)&Q,  g_Q);
    cudaGetSymbolAddress((void**)&P,  g_P);

    cudaFuncSetAttribute(solver_kernel,
                         cudaFuncAttributeMaxDynamicSharedMemorySize, SMEM_BYTES);

    precompute_fused<<<dim3(8, 16, 3), 256>>>(b, cin, W1, b1, Aaug, Ainv, X1, Q, P);
    gemm_kernel<<<dim3(8, 16), 256>>>(X1, nullptr, W2, b2, X2, BATCH, HDIM, HDIM, 1, 0, 0);
    gemm_kernel<<<dim3(8, 16), 256>>>(X2, nullptr, W3, b3, Ys, BATCH, DTOT, HDIM, 2, 0, 0);
    for (int ch = 0; ch < NCHUNK; ch++)
        solver_kernel<<<SOLVER_CTAS, NTHR, SMEM_BYTES>>>(out, ch * CHUNK, (ch + 1) * CHUNK);
}

// round 7
// speedup vs baseline: 1.2762x; 1.2762x over previous
#include <cuda_runtime.h>
#include <math.h>

// ---------------------------------------------------------------------------
// HardConstrainedMLP. proj_pinv(s) = s @ P + Q.
// Solver (per CTA: 8 batch rows, 512 threads, 16 warps):
//   warp w -> kgroup g = w&3 (128 k each, k padded to 512),
//             colgroup cg = w>>2 (128 cols each, cols padded to 512).
//   Thread (g,cg,lane) owns 4 columns x 8 rows over its k-quarter:
//   k-parity FFMA2 (fma.rn.f32x2), P stored k-pair interleaved:
//     g_P[kp*1024 + 2c + parity] = P[2kp+parity][c]
//   Partial z exchanged via smem Pz[4][8][512]; combine + SOC + S update
//   spread over all 512 threads (c = t).
//   S redundancy across warps cut 4x -> smem crossbar below fma floor.
// ---------------------------------------------------------------------------

#define BATCH       1024
#define MDIM        250
#define DTOT        500
#define HDIM        512
#define NITER       1000
#define NCHUNK      4
#define CHUNK       (NITER / NCHUNK)
#define ROWS_PER_CTA 8
#define SOLVER_CTAS (BATCH / ROWS_PER_CTA)
#define NTHR        512
#define KPC         6        // cached k-pairs per kgroup (24 total = 96KB)
#define KPS         58       // streamed k-pairs per kgroup (29 2-kp steps)

#define OMEGA_F 1.8f
#define ALPHA_F (1.0f / 1.2f)

typedef unsigned long long ull;

#define FFMA2(d, a, b) \
    asm("fma.rn.f32x2 %0, %1, %2, %0;" : "+l"(d) : "l"(a), "l"(b))

__device__ __forceinline__ float2 f32x2_unpack(ull v) {
    float2 r;
    asm("mov.b64 {%0, %1}, %2;" : "=f"(r.x), "=f"(r.y) : "l"(v));
    return r;
}

// Scratch (device globals; zero-initialized, no runtime allocation)
__device__ float g_X1 [BATCH * HDIM];
__device__ float g_X2 [BATCH * HDIM];
__device__ float g_Ys [BATCH * DTOT];
__device__ float g_Q  [BATCH * DTOT];
__device__ float g_S  [BATCH * DTOT];
__device__ float g_P  [256 * 1024];     // 256 kp x (512 cols x 2); pad = 0

// ---------------------------------------------------------------------------
// Precompute GEMM (as R5).
// ---------------------------------------------------------------------------
__device__ void gemm_dev(const float* __restrict__ A, const float* __restrict__ A2,
                         const float* __restrict__ B, const float* __restrict__ bias,
                         float* __restrict__ C,
                         int M, int N, int K, int mode, int bT, int aT)
{
    __shared__ float As[16][64];
    __shared__ float Bs[16][68];
    const int tid = threadIdx.x;
    const int tx = tid & 15, ty = tid >> 4;
    const int m0 = blockIdx.y * 64, n0 = blockIdx.x * 64;

    float acc[4][4];
    #pragma unroll
    for (int i = 0; i < 4; i++)
        #pragma unroll
        for (int j = 0; j < 4; j++) acc[i][j] = 0.f;

    for (int k0 = 0; k0 < K; k0 += 16) {
        #pragma unroll
        for (int i = 0; i < 4; i++) {
            int idx = tid + i * 256;
            int mr = idx >> 4, kk = idx & 15;
            int mg = m0 + mr, kg = k0 + kk;
            float av = 0.f;
            if (mg < M && kg < K) {
                if (aT)       av = A[(size_t)kg * M + mg];
                else if (A2)  av = (kg < MDIM) ? A[(size_t)mg * MDIM + kg]
                                               : A2[(size_t)mg * MDIM + (kg - MDIM)];
                else          av = A[(size_t)mg * K + kg];
            }
            As[kk][mr] = av;
        }
        #pragma unroll
        for (int i = 0; i < 4; i++) {
            int idx = tid + i * 256;
            if (!bT) {
                int kk = idx >> 6, cg = idx & 63;
                int kgl = k0 + kk, cgl = n0 + cg;
                Bs[kk][cg] = (kgl < K && cgl < N) ? B[(size_t)kgl * N + cgl] : 0.f;
            } else {
                int cg = idx >> 4, kk = idx & 15;
                int kgl = k0 + kk, cgl = n0 + cg;
                Bs[kk][cg] = (kgl < K && cgl < N) ? B[(size_t)cgl * K + kgl] : 0.f;
            }
        }
        __syncthreads();
        #pragma unroll
        for (int kk = 0; kk < 16; kk++) {
            float a[4], bb[4];
            #pragma unroll
            for (int i = 0; i < 4; i++) a[i] = As[kk][ty * 4 + i];
            #pragma unroll
            for (int j = 0; j < 4; j++) bb[j] = Bs[kk][tx * 4 + j];
            #pragma unroll
            for (int i = 0; i < 4; i++)
                #pragma unroll
                for (int j = 0; j < 4; j++) acc[i][j] += a[i] * bb[j];
        }
        __syncthreads();
    }

    #pragma unroll
    for (int i = 0; i < 4; i++) {
        int mg = m0 + ty * 4 + i;
        if (mg >= M) continue;
        #pragma unroll
        for (int j = 0; j < 4; j++) {
            int ng = n0 + tx * 4 + j;
            if (ng >= N) continue;
            float v = acc[i][j];
            if (bias) v += bias[ng];
            if (mode == 1)      v = fmaxf(v, 0.f);
            else if (mode == 2) v *= (1.0f / 6.0f);
            if (mode == 4) {
                v = ((mg == ng) ? 1.f : 0.f) - v;
                C[(size_t)(mg >> 1) * 1024 + ng * 2 + (mg & 1)] = v;
            } else {
                C[(size_t)mg * N + ng] = v;
            }
        }
    }
}

__global__ void gemm_kernel(const float* __restrict__ A, const float* __restrict__ A2,
                            const float* __restrict__ B, const float* __restrict__ bias,
                            float* __restrict__ C,
                            int M, int N, int K, int mode, int bT, int aT)
{
    gemm_dev(A, A2, B, bias, C, M, N, K, mode, bT, aT);
}

__global__ void precompute_fused(const float* b, const float* cin,
                                 const float* W1, const float* b1,
                                 const float* Aaug, const float* Ainv,
                                 float* X1, float* Q, float* P)
{
    int z = blockIdx.z;
    if (z == 0) {
        gemm_dev(b, cin, W1, b1, X1, BATCH, HDIM, DTOT, 1, 0, 0);
    } else if (z == 1) {
        gemm_dev(b, nullptr, Ainv, nullptr, Q, BATCH, DTOT, MDIM, 0, 1, 0);
    } else {
        if (blockIdx.y >= 8) return;
        gemm_dev(Aaug, nullptr, Ainv, nullptr, P, DTOT, DTOT, MDIM, 4, 1, 1);
    }
}

// ---------------------------------------------------------------------------
// Solver smem (floats):
//  Ssm[8*512]=4096 | Qsm 4096 | Ysm 4096 | Pz[4*4096]=16384 |
//  red[128] nrm[8] tls[8] pad->28832 | Pcs[24*1024]=24576     (213,632 B)
// ---------------------------------------------------------------------------
#define SMEM_FLOATS (28832 + 24 * 1024)
#define SMEM_BYTES  (SMEM_FLOATS * 4)

__device__ __forceinline__ float soc_elem(float tp, int c, float nu, float tt)
{
    if (c < MDIM) return tp;
    if (nu <= tt) return tp;
    if (nu <= -tt) return 0.f;
    float h = 0.5f * (tt + nu);
    return (c == DTOT - 1) ? h : h * tp / (nu + 1e-12f);
}

// 8 FFMA2 for one 2-kp step, one row r: sv covers k-pairs kp0,kp0+1.
#define ROW_STEP(r, sv, a0, a1, b0, b1)              \
    FFMA2(acc[r][0], (sv).x, (a0).x);                \
    FFMA2(acc[r][1], (sv).x, (a0).y);                \
    FFMA2(acc[r][2], (sv).x, (a1).x);                \
    FFMA2(acc[r][3], (sv).x, (a1).y);                \
    FFMA2(acc[r][0], (sv).y, (b0).x);                \
    FFMA2(acc[r][1], (sv).y, (b0).y);                \
    FFMA2(acc[r][2], (sv).y, (b1).x);                \
    FFMA2(acc[r][3], (sv).y, (b1).y)

// Partial z over kgroup g's 128 k for this thread's 4 cols x 8 rows; store to Pz.
__device__ __forceinline__ void gemm_partial(const float* __restrict__ Ssm,
                                             const float* __restrict__ Pcs,
                                             float* __restrict__ Pz,
                                             int g, int cg, int lane)
{
    const int cbase = cg * 128 + lane * 4;
    const int cb2   = cbase * 2;

    ull acc[8][4];
    #pragma unroll
    for (int r = 0; r < 8; r++)
        #pragma unroll
        for (int j = 0; j < 4; j++) acc[r][j] = 0ull;

    // ---- cached k-pairs: global kp = 64g + j, j in [0,6) ----
    #pragma unroll 1
    for (int j = 0; j < KPC; j += 2) {
        const float* p0 = &Pcs[(g * KPC + j) * 1024 + cb2];
        const float* p1 = p0 + 1024;
        ulonglong2 a0 = *reinterpret_cast<const ulonglong2*>(p0);
        ulonglong2 a1 = *reinterpret_cast<const ulonglong2*>(p0 + 4);
        ulonglong2 b0 = *reinterpret_cast<const ulonglong2*>(p1);
        ulonglong2 b1 = *reinterpret_cast<const ulonglong2*>(p1 + 4);
        const int kp0 = g * 64 + j;
        #pragma unroll
        for (int r = 0; r < 8; r++) {
            ulonglong2 sv = *reinterpret_cast<const ulonglong2*>(&Ssm[r * 512 + 2 * kp0]);
            ROW_STEP(r, sv, a0, a1, b0, b1);
        }
    }

    // ---- streamed k-pairs: global kp = 64g + 6 + [0,58), 29 2-kp steps ----
    const float* Pg = &g_P[(g * 64 + KPC) * 1024 + cb2];
    ulonglong2 buf[2][4];
    buf[0][0] = *reinterpret_cast<const ulonglong2*>(Pg);
    buf[0][1] = *reinterpret_cast<const ulonglong2*>(Pg + 4);
    buf[0][2] = *reinterpret_cast<const ulonglong2*>(Pg + 1024);
    buf[0][3] = *reinterpret_cast<const ulonglong2*>(Pg + 1024 + 4);
    #pragma unroll 2
    for (int s = 0; s < KPS / 2; s++) {
        const int cur = s & 1;
        if (s + 1 < KPS / 2) {
            const float* nxt = Pg + (2 * s + 2) * 1024;
            buf[cur ^ 1][0] = *reinterpret_cast<const ulonglong2*>(nxt);
            buf[cur ^ 1][1] = *reinterpret_cast<const ulonglong2*>(nxt + 4);
            buf[cur ^ 1][2] = *reinterpret_cast<const ulonglong2*>(nxt + 1024);
            buf[cur ^ 1][3] = *reinterpret_cast<const ulonglong2*>(nxt + 1024 + 4);
        }
        const int kp0 = g * 64 + KPC + 2 * s;
        #pragma unroll
        for (int r = 0; r < 8; r++) {
            ulonglong2 sv = *reinterpret_cast<const ulonglong2*>(&Ssm[r * 512 + 2 * kp0]);
            ROW_STEP(r, sv, buf[cur][0], buf[cur][1], buf[cur][2], buf[cur][3]);
        }
    }

    // ---- reduce k-parity and store partials ----
    float* dst = &Pz[g * 4096 + cbase];
    #pragma unroll
    for (int r = 0; r < 8; r++) {
        float2 u0 = f32x2_unpack(acc[r][0]);
        float2 u1 = f32x2_unpack(acc[r][1]);
        float2 u2 = f32x2_unpack(acc[r][2]);
        float2 u3 = f32x2_unpack(acc[r][3]);
        float2 v0; v0.x = u0.x + u0.y; v0.y = u1.x + u1.y;
        float2 v1; v1.x = u2.x + u2.y; v1.y = u3.x + u3.y;
        *reinterpret_cast<float2*>(&dst[r * 512])     = v0;
        *reinterpret_cast<float2*>(&dst[r * 512 + 2]) = v1;
    }
}

__global__ void __launch_bounds__(NTHR, 1) solver_kernel(float* __restrict__ out,
                                                         int start_it, int end_it)
{
    extern __shared__ float sm[];
    float* Ssm = sm;              // 4096
    float* Qsm = sm + 4096;       // 4096
    float* Ysm = sm + 8192;       // 4096
    float* Pz  = sm + 12288;      // 16384
    float* red = sm + 28672;      // 128
    float* nrm = sm + 28800;      // 8
    float* tls = sm + 28808;      // 8
    float* Pcs = sm + 28832;      // 24*1024

    const int t = threadIdx.x;
    const int w = t >> 5, lane = t & 31;
    const int g = w & 3, cg = w >> 2;
    const int row0 = blockIdx.x * ROWS_PER_CTA;
    const int c = t;
    const bool act = (c < DTOT);

    // init: S (strided, zero-padded), Q, Ys
    for (int i = t; i < ROWS_PER_CTA * 512; i += NTHR) {
        int r = i >> 9, cc = i & 511;
        float sv = 0.f, qv = 0.f, yv = 0.f;
        if (cc < DTOT) {
            if (start_it != 0) sv = g_S[(row0 + r) * DTOT + cc];
            qv = g_Q [(row0 + r) * DTOT + cc];
            yv = g_Ys[(row0 + r) * DTOT + cc];
        }
        Ssm[i] = sv; Qsm[i] = qv; Ysm[i] = yv;
    }
    // P cache: slot -> global kp = (slot/6)*64 + slot%6
    {
        float4* dstv = reinterpret_cast<float4*>(Pcs);
        #pragma unroll 1
        for (int i4 = t; i4 < 24 * 256; i4 += NTHR) {
            int slot = i4 >> 8, within = i4 & 255;
            int kp = (slot / KPC) * 64 + (slot % KPC);
            dstv[i4] = *reinterpret_cast<const float4*>(&g_P[kp * 1024 + within * 4]);
        }
    }
    __syncthreads();

    for (int it = start_it; it < end_it; ++it) {
        gemm_partial(Ssm, Pcs, Pz, g, cg, lane);
        __syncthreads();                               // B1: partials ready

        // combine + elementwise, thread owns column c
        float z[8], tp[8], sold[8], val[8];
        const bool in_u = act && (c >= MDIM) && (c != DTOT - 1);
        #pragma unroll
        for (int r = 0; r < 8; r++) {
            if (act) {
                z[r] = Pz[r * 512 + c] + Pz[4096 + r * 512 + c]
                     + Pz[8192 + r * 512 + c] + Pz[12288 + r * 512 + c]
                     + Qsm[r * 512 + c];
                sold[r] = Ssm[r * 512 + c];
                tp[r] = ALPHA_F * (2.f * z[r] - sold[r]) - Ysm[r * 512 + c];
                val[r] = in_u ? tp[r] * tp[r] : 0.f;
            } else { z[r] = 0.f; tp[r] = 0.f; sold[r] = 0.f; val[r] = 0.f; }
        }
        #pragma unroll
        for (int off = 16; off; off >>= 1)
            #pragma unroll
            for (int r = 0; r < 8; r++)
                val[r] += __shfl_down_sync(0xffffffffu, val[r], off);
        if (lane == 0) {
            #pragma unroll
            for (int r = 0; r < 8; r++) red[w * 8 + r] = val[r];
        }
        if (t == DTOT - 1) {
            #pragma unroll
            for (int r = 0; r < 8; r++) tls[r] = tp[r];
        }
        __syncthreads();                               // B2
        if (w < 8 && lane < 16) {                      // warp w reduces row w
            float s = red[lane * 8 + w];
            #pragma unroll
            for (int off = 8; off; off >>= 1)
                s += __shfl_down_sync(0x0000ffffu, s, off);
            if (lane == 0) nrm[w] = sqrtf(s);
        }
        __syncthreads();                               // B3
        if (act) {
            #pragma unroll
            for (int r = 0; r < 8; r++) {
                float tk = soc_elem(tp[r], c, nrm[r], tls[r]);
                Ssm[r * 512 + c] = sold[r] + OMEGA_F * (tk - z[r]);
            }
        }
        __syncthreads();                               // B4
    }

    if (end_it == NITER) {
        // final z = proj_pinv(s_K)
        gemm_partial(Ssm, Pcs, Pz, g, cg, lane);
        __syncthreads();
        if (act) {
            #pragma unroll
            for (int r = 0; r < 8; r++) {
                float zv = Pz[r * 512 + c] + Pz[4096 + r * 512 + c]
                         + Pz[8192 + r * 512 + c] + Pz[12288 + r * 512 + c]
                         + Qsm[r * 512 + c];
                out[(row0 + r) * DTOT + c] = zv;
            }
        }
    } else if (act) {
        #pragma unroll
        for (int r = 0; r < 8; r++)
            g_S[(row0 + r) * DTOT + c] = Ssm[r * 512 + c];
    }
}

// ---------------------------------------------------------------------------
extern "C" void kernel_launch(void* const* d_in, const int* in_sizes, int n_in,
                              void* d_out, int out_size)
{
    const float* b    = (const float*)d_in[0];
    const float* cin  = (const float*)d_in[1];
    const float* W1   = (const float*)d_in[2];
    const float* b1   = (const float*)d_in[3];
    const float* W2   = (const float*)d_in[4];
    const float* b2   = (const float*)d_in[5];
    const float* W3   = (const float*)d_in[6];
    const float* b3   = (const float*)d_in[7];
    const float* Aaug = (const float*)d_in[8];
    const float* Ainv = (const float*)d_in[9];
    float* out = (float*)d_out;

    float *X1, *X2, *Ys, *Q, *P;
    cudaGetSymbolAddress((void**)&X1, g_X1);
    cudaGetSymbolAddress((void**)&X2, g_X2);
    cudaGetSymbolAddress((void**)&Ys, g_Ys);
    cudaGetSymbolAddress((void**)&Q,  g_Q);
    cudaGetSymbolAddress((void**)&P,  g_P);

    cudaFuncSetAttribute(solver_kernel,
                         cudaFuncAttributeMaxDynamicSharedMemorySize, SMEM_BYTES);

    precompute_fused<<<dim3(8, 16, 3), 256>>>(b, cin, W1, b1, Aaug, Ainv, X1, Q, P);
    gemm_kernel<<<dim3(8, 16), 256>>>(X1, nullptr, W2, b2, X2, BATCH, HDIM, HDIM, 1, 0, 0);
    gemm_kernel<<<dim3(8, 16), 256>>>(X2, nullptr, W3, b3, Ys, BATCH, DTOT, HDIM, 2, 0, 0);
    for (int ch = 0; ch < NCHUNK; ch++)
        solver_kernel<<<SOLVER_CTAS, NTHR, SMEM_BYTES>>>(out, ch * CHUNK, (ch + 1) * CHUNK);
}

// round 8
// speedup vs baseline: 1.2763x; 1.0001x over previous
#include <cuda_runtime.h>
#include <math.h>

// ---------------------------------------------------------------------------
// HardConstrainedMLP. proj_pinv(s) = s @ P + Q.
// Solver (per CTA: 8 batch rows, 512 threads, 16 warps):
//   warp w -> kgroup g = w&3 (128 k each, k padded to 512),
//             colgroup cg = w>>2 (128 cols each, cols padded to 512).
//   Thread (g,cg,lane) owns 4 columns x 8 rows over its k-quarter:
//   k-parity FFMA2 (fma.rn.f32x2), P stored k-pair interleaved:
//     g_P[kp*1024 + 2c + parity] = P[2kp+parity][c]
//   Partial z exchanged via smem Pz[4][8][512]; combine + SOC + S update
//   spread over all 512 threads (c = t).
//   S redundancy across warps cut 4x -> smem crossbar below fma floor.
// ---------------------------------------------------------------------------

#define BATCH       1024
#define MDIM        250
#define DTOT        500
#define HDIM        512
#define NITER       1000
#define NCHUNK      4
#define CHUNK       (NITER / NCHUNK)
#define ROWS_PER_CTA 8
#define SOLVER_CTAS (BATCH / ROWS_PER_CTA)
#define NTHR        512
#define KPC         6        // cached k-pairs per kgroup (24 total = 96KB)
#define KPS         58       // streamed k-pairs per kgroup (29 2-kp steps)

#define OMEGA_F 1.8f
#define ALPHA_F (1.0f / 1.2f)

typedef unsigned long long ull;

#define FFMA2(d, a, b) \
    asm("fma.rn.f32x2 %0, %1, %2, %0;" : "+l"(d) : "l"(a), "l"(b))

__device__ __forceinline__ float2 f32x2_unpack(ull v) {
    float2 r;
    asm("mov.b64 {%0, %1}, %2;" : "=f"(r.x), "=f"(r.y) : "l"(v));
    return r;
}

// Scratch (device globals; zero-initialized, no runtime allocation)
__device__ float g_X1 [BATCH * HDIM];
__device__ float g_X2 [BATCH * HDIM];
__device__ float g_Ys [BATCH * DTOT];
__device__ float g_Q  [BATCH * DTOT];
__device__ float g_S  [BATCH * DTOT];
__device__ float g_P  [256 * 1024];     // 256 kp x (512 cols x 2); pad = 0

// ---------------------------------------------------------------------------
// Precompute GEMM (as R5).
// ---------------------------------------------------------------------------
__device__ void gemm_dev(const float* __restrict__ A, const float* __restrict__ A2,
                         const float* __restrict__ B, const float* __restrict__ bias,
                         float* __restrict__ C,
                         int M, int N, int K, int mode, int bT, int aT)
{
    __shared__ float As[16][64];
    __shared__ float Bs[16][68];
    const int tid = threadIdx.x;
    const int tx = tid & 15, ty = tid >> 4;
    const int m0 = blockIdx.y * 64, n0 = blockIdx.x * 64;

    float acc[4][4];
    #pragma unroll
    for (int i = 0; i < 4; i++)
        #pragma unroll
        for (int j = 0; j < 4; j++) acc[i][j] = 0.f;

    for (int k0 = 0; k0 < K; k0 += 16) {
        #pragma unroll
        for (int i = 0; i < 4; i++) {
            int idx = tid + i * 256;
            int mr = idx >> 4, kk = idx & 15;
            int mg = m0 + mr, kg = k0 + kk;
            float av = 0.f;
            if (mg < M && kg < K) {
                if (aT)       av = A[(size_t)kg * M + mg];
                else if (A2)  av = (kg < MDIM) ? A[(size_t)mg * MDIM + kg]
                                               : A2[(size_t)mg * MDIM + (kg - MDIM)];
                else          av = A[(size_t)mg * K + kg];
            }
            As[kk][mr] = av;
        }
        #pragma unroll
        for (int i = 0; i < 4; i++) {
            int idx = tid + i * 256;
            if (!bT) {
                int kk = idx >> 6, cg = idx & 63;
                int kgl = k0 + kk, cgl = n0 + cg;
                Bs[kk][cg] = (kgl < K && cgl < N) ? B[(size_t)kgl * N + cgl] : 0.f;
            } else {
                int cg = idx >> 4, kk = idx & 15;
                int kgl = k0 + kk, cgl = n0 + cg;
                Bs[kk][cg] = (kgl < K && cgl < N) ? B[(size_t)cgl * K + kgl] : 0.f;
            }
        }
        __syncthreads();
        #pragma unroll
        for (int kk = 0; kk < 16; kk++) {
            float a[4], bb[4];
            #pragma unroll
            for (int i = 0; i < 4; i++) a[i] = As[kk][ty * 4 + i];
            #pragma unroll
            for (int j = 0; j < 4; j++) bb[j] = Bs[kk][tx * 4 + j];
            #pragma unroll
            for (int i = 0; i < 4; i++)
                #pragma unroll
                for (int j = 0; j < 4; j++) acc[i][j] += a[i] * bb[j];
        }
        __syncthreads();
    }

    #pragma unroll
    for (int i = 0; i < 4; i++) {
        int mg = m0 + ty * 4 + i;
        if (mg >= M) continue;
        #pragma unroll
        for (int j = 0; j < 4; j++) {
            int ng = n0 + tx * 4 + j;
            if (ng >= N) continue;
            float v = acc[i][j];
            if (bias) v += bias[ng];
            if (mode == 1)      v = fmaxf(v, 0.f);
            else if (mode == 2) v *= (1.0f / 6.0f);
            if (mode == 4) {
                v = ((mg == ng) ? 1.f : 0.f) - v;
                C[(size_t)(mg >> 1) * 1024 + ng * 2 + (mg & 1)] = v;
            } else {
                C[(size_t)mg * N + ng] = v;
            }
        }
    }
}

__global__ void gemm_kernel(const float* __restrict__ A, const float* __restrict__ A2,
                            const float* __restrict__ B, const float* __restrict__ bias,
                            float* __restrict__ C,
                            int M, int N, int K, int mode, int bT, int aT)
{
    gemm_dev(A, A2, B, bias, C, M, N, K, mode, bT, aT);
}

__global__ void precompute_fused(const float* b, const float* cin,
                                 const float* W1, const float* b1,
                                 const float* Aaug, const float* Ainv,
                                 float* X1, float* Q, float* P)
{
    int z = blockIdx.z;
    if (z == 0) {
        gemm_dev(b, cin, W1, b1, X1, BATCH, HDIM, DTOT, 1, 0, 0);
    } else if (z == 1) {
        gemm_dev(b, nullptr, Ainv, nullptr, Q, BATCH, DTOT, MDIM, 0, 1, 0);
    } else {
        if (blockIdx.y >= 8) return;
        gemm_dev(Aaug, nullptr, Ainv, nullptr, P, DTOT, DTOT, MDIM, 4, 1, 1);
    }
}

// ---------------------------------------------------------------------------
// Solver smem (floats):
//  Ssm[8*512]=4096 | Qsm 4096 | Ysm 4096 | Pz[4*4096]=16384 |
//  red[128] nrm[8] tls[8] pad->28832 | Pcs[24*1024]=24576     (213,632 B)
// ---------------------------------------------------------------------------
#define SMEM_FLOATS (28832 + 24 * 1024)
#define SMEM_BYTES  (SMEM_FLOATS * 4)

__device__ __forceinline__ float soc_elem(float tp, int c, float nu, float tt)
{
    if (c < MDIM) return tp;
    if (nu <= tt) return tp;
    if (nu <= -tt) return 0.f;
    float h = 0.5f * (tt + nu);
    return (c == DTOT - 1) ? h : h * tp / (nu + 1e-12f);
}

// 8 FFMA2 for one 2-kp step, one row r: sv covers k-pairs kp0,kp0+1.
#define ROW_STEP(r, sv, a0, a1, b0, b1)              \
    FFMA2(acc[r][0], (sv).x, (a0).x);                \
    FFMA2(acc[r][1], (sv).x, (a0).y);                \
    FFMA2(acc[r][2], (sv).x, (a1).x);                \
    FFMA2(acc[r][3], (sv).x, (a1).y);                \
    FFMA2(acc[r][0], (sv).y, (b0).x);                \
    FFMA2(acc[r][1], (sv).y, (b0).y);                \
    FFMA2(acc[r][2], (sv).y, (b1).x);                \
    FFMA2(acc[r][3], (sv).y, (b1).y)

// Partial z over kgroup g's 128 k for this thread's 4 cols x 8 rows; store to Pz.
__device__ __forceinline__ void gemm_partial(const float* __restrict__ Ssm,
                                             const float* __restrict__ Pcs,
                                             float* __restrict__ Pz,
                                             int g, int cg, int lane)
{
    const int cbase = cg * 128 + lane * 4;
    const int cb2   = cbase * 2;

    ull acc[8][4];
    #pragma unroll
    for (int r = 0; r < 8; r++)
        #pragma unroll
        for (int j = 0; j < 4; j++) acc[r][j] = 0ull;

    // ---- cached k-pairs: global kp = 64g + j, j in [0,6) ----
    #pragma unroll 1
    for (int j = 0; j < KPC; j += 2) {
        const float* p0 = &Pcs[(g * KPC + j) * 1024 + cb2];
        const float* p1 = p0 + 1024;
        ulonglong2 a0 = *reinterpret_cast<const ulonglong2*>(p0);
        ulonglong2 a1 = *reinterpret_cast<const ulonglong2*>(p0 + 4);
        ulonglong2 b0 = *reinterpret_cast<const ulonglong2*>(p1);
        ulonglong2 b1 = *reinterpret_cast<const ulonglong2*>(p1 + 4);
        const int kp0 = g * 64 + j;
        #pragma unroll
        for (int r = 0; r < 8; r++) {
            ulonglong2 sv = *reinterpret_cast<const ulonglong2*>(&Ssm[r * 512 + 2 * kp0]);
            ROW_STEP(r, sv, a0, a1, b0, b1);
        }
    }

    // ---- streamed k-pairs: global kp = 64g + 6 + [0,58), 29 2-kp steps ----
    const float* Pg = &g_P[(g * 64 + KPC) * 1024 + cb2];
    ulonglong2 buf[2][4];
    buf[0][0] = *reinterpret_cast<const ulonglong2*>(Pg);
    buf[0][1] = *reinterpret_cast<const ulonglong2*>(Pg + 4);
    buf[0][2] = *reinterpret_cast<const ulonglong2*>(Pg + 1024);
    buf[0][3] = *reinterpret_cast<const ulonglong2*>(Pg + 1024 + 4);
    #pragma unroll 2
    for (int s = 0; s < KPS / 2; s++) {
        const int cur = s & 1;
        if (s + 1 < KPS / 2) {
            const float* nxt = Pg + (2 * s + 2) * 1024;
            buf[cur ^ 1][0] = *reinterpret_cast<const ulonglong2*>(nxt);
            buf[cur ^ 1][1] = *reinterpret_cast<const ulonglong2*>(nxt + 4);
            buf[cur ^ 1][2] = *reinterpret_cast<const ulonglong2*>(nxt + 1024);
            buf[cur ^ 1][3] = *reinterpret_cast<const ulonglong2*>(nxt + 1024 + 4);
        }
        const int kp0 = g * 64 + KPC + 2 * s;
        #pragma unroll
        for (int r = 0; r < 8; r++) {
            ulonglong2 sv = *reinterpret_cast<const ulonglong2*>(&Ssm[r * 512 + 2 * kp0]);
            ROW_STEP(r, sv, buf[cur][0], buf[cur][1], buf[cur][2], buf[cur][3]);
        }
    }

    // ---- reduce k-parity and store partials ----
    float* dst = &Pz[g * 4096 + cbase];
    #pragma unroll
    for (int r = 0; r < 8; r++) {
        float2 u0 = f32x2_unpack(acc[r][0]);
        float2 u1 = f32x2_unpack(acc[r][1]);
        float2 u2 = f32x2_unpack(acc[r][2]);
        float2 u3 = f32x2_unpack(acc[r][3]);
        float2 v0; v0.x = u0.x + u0.y; v0.y = u1.x + u1.y;
        float2 v1; v1.x = u2.x + u2.y; v1.y = u3.x + u3.y;
        *reinterpret_cast<float2*>(&dst[r * 512])     = v0;
        *reinterpret_cast<float2*>(&dst[r * 512 + 2]) = v1;
    }
}

__global__ void __launch_bounds__(NTHR, 1) solver_kernel(float* __restrict__ out,
                                                         int start_it, int end_it)
{
    extern __shared__ float sm[];
    float* Ssm = sm;              // 4096
    float* Qsm = sm + 4096;       // 4096
    float* Ysm = sm + 8192;       // 4096
    float* Pz  = sm + 12288;      // 16384
    float* red = sm + 28672;      // 128
    float* nrm = sm + 28800;      // 8
    float* tls = sm + 28808;      // 8
    float* Pcs = sm + 28832;      // 24*1024

    const int t = threadIdx.x;
    const int w = t >> 5, lane = t & 31;
    const int g = w & 3, cg = w >> 2;
    const int row0 = blockIdx.x * ROWS_PER_CTA;
    const int c = t;
    const bool act = (c < DTOT);

    // init: S (strided, zero-padded), Q, Ys
    for (int i = t; i < ROWS_PER_CTA * 512; i += NTHR) {
        int r = i >> 9, cc = i & 511;
        float sv = 0.f, qv = 0.f, yv = 0.f;
        if (cc < DTOT) {
            if (start_it != 0) sv = g_S[(row0 + r) * DTOT + cc];
            qv = g_Q [(row0 + r) * DTOT + cc];
            yv = g_Ys[(row0 + r) * DTOT + cc];
        }
        Ssm[i] = sv; Qsm[i] = qv; Ysm[i] = yv;
    }
    // P cache: slot -> global kp = (slot/6)*64 + slot%6
    {
        float4* dstv = reinterpret_cast<float4*>(Pcs);
        #pragma unroll 1
        for (int i4 = t; i4 < 24 * 256; i4 += NTHR) {
            int slot = i4 >> 8, within = i4 & 255;
            int kp = (slot / KPC) * 64 + (slot % KPC);
            dstv[i4] = *reinterpret_cast<const float4*>(&g_P[kp * 1024 + within * 4]);
        }
    }
    __syncthreads();

    for (int it = start_it; it < end_it; ++it) {
        gemm_partial(Ssm, Pcs, Pz, g, cg, lane);
        __syncthreads();                               // B1: partials ready

        // combine + elementwise, thread owns column c
        float z[8], tp[8], sold[8], val[8];
        const bool in_u = act && (c >= MDIM) && (c != DTOT - 1);
        #pragma unroll
        for (int r = 0; r < 8; r++) {
            if (act) {
                z[r] = Pz[r * 512 + c] + Pz[4096 + r * 512 + c]
                     + Pz[8192 + r * 512 + c] + Pz[12288 + r * 512 + c]
                     + Qsm[r * 512 + c];
                sold[r] = Ssm[r * 512 + c];
                tp[r] = ALPHA_F * (2.f * z[r] - sold[r]) - Ysm[r * 512 + c];
                val[r] = in_u ? tp[r] * tp[r] : 0.f;
            } else { z[r] = 0.f; tp[r] = 0.f; sold[r] = 0.f; val[r] = 0.f; }
        }
        #pragma unroll
        for (int off = 16; off; off >>= 1)
            #pragma unroll
            for (int r = 0; r < 8; r++)
                val[r] += __shfl_down_sync(0xffffffffu, val[r], off);
        if (lane == 0) {
            #pragma unroll
            for (int r = 0; r < 8; r++) red[w * 8 + r] = val[r];
        }
        if (t == DTOT - 1) {
            #pragma unroll
            for (int r = 0; r < 8; r++) tls[r] = tp[r];
        }
        __syncthreads();                               // B2
        if (w < 8 && lane < 16) {                      // warp w reduces row w
            float s = red[lane * 8 + w];
            #pragma unroll
            for (int off = 8; off; off >>= 1)
                s += __shfl_down_sync(0x0000ffffu, s, off);
            if (lane == 0) nrm[w] = sqrtf(s);
        }
        __syncthreads();                               // B3
        if (act) {
            #pragma unroll
            for (int r = 0; r < 8; r++) {
                float tk = soc_elem(tp[r], c, nrm[r], tls[r]);
                Ssm[r * 512 + c] = sold[r] + OMEGA_F * (tk - z[r]);
            }
        }
        __syncthreads();                               // B4
    }

    if (end_it == NITER) {
        // final z = proj_pinv(s_K)
        gemm_partial(Ssm, Pcs, Pz, g, cg, lane);
        __syncthreads();
        if (act) {
            #pragma unroll
            for (int r = 0; r < 8; r++) {
                float zv = Pz[r * 512 + c] + Pz[4096 + r * 512 + c]
                         + Pz[8192 + r * 512 + c] + Pz[12288 + r * 512 + c]
                         + Qsm[r * 512 + c];
                out[(row0 + r) * DTOT + c] = zv;
            }
        }
    } else if (act) {
        #pragma unroll
        for (int r = 0; r < 8; r++)
            g_S[(row0 + r) * DTOT + c] = Ssm[r * 512 + c];
    }
}

// ---------------------------------------------------------------------------
extern "C" void kernel_launch(void* const* d_in, const int* in_sizes, int n_in,
                              void* d_out, int out_size)
{
    const float* b    = (const float*)d_in[0];
    const float* cin  = (const float*)d_in[1];
    const float* W1   = (const float*)d_in[2];
    const float* b1   = (const float*)d_in[3];
    const float* W2   = (const float*)d_in[4];
    const float* b2   = (const float*)d_in[5];
    const float* W3   = (const float*)d_in[6];
    const float* b3   = (const float*)d_in[7];
    const float* Aaug = (const float*)d_in[8];
    const float* Ainv = (const float*)d_in[9];
    float* out = (float*)d_out;

    float *X1, *X2, *Ys, *Q, *P;
    cudaGetSymbolAddress((void**)&X1, g_X1);
    cudaGetSymbolAddress((void**)&X2, g_X2);
    cudaGetSymbolAddress((void**)&Ys, g_Ys);
    cudaGetSymbolAddress((void**)&Q,  g_Q);
    cudaGetSymbolAddress((void**)&P,  g_P);

    cudaFuncSetAttribute(solver_kernel,
                         cudaFuncAttributeMaxDynamicSharedMemorySize, SMEM_BYTES);

    precompute_fused<<<dim3(8, 16, 3), 256>>>(b, cin, W1, b1, Aaug, Ainv, X1, Q, P);
    gemm_kernel<<<dim3(8, 16), 256>>>(X1, nullptr, W2, b2, X2, BATCH, HDIM, HDIM, 1, 0, 0);
    gemm_kernel<<<dim3(8, 16), 256>>>(X2, nullptr, W3, b3, Ys, BATCH, DTOT, HDIM, 2, 0, 0);
    for (int ch = 0; ch < NCHUNK; ch++)
        solver_kernel<<<SOLVER_CTAS, NTHR, SMEM_BYTES>>>(out, ch * CHUNK, (ch + 1) * CHUNK);
}

// round 9
// speedup vs baseline: 1.5536x; 1.2173x over previous
#include <cuda_runtime.h>
#include <math.h>

// ---------------------------------------------------------------------------
// HardConstrainedMLP. proj_pinv(s) = s @ P + Q.
// Solver (per CTA: 8 batch rows, 512 threads, 16 warps):
//   warp w -> kgroup g = w&3 (128 k), colgroup cg = w>>2 (128 cols).
//   Thread owns 4 cols x 8 rows over its k-quarter; k-parity FFMA2.
//   P (k-pair interleaved: g_P[kp*1024 + 2c + parity]) is streamed through a
//   warp-private 4-slot cp.async smem ring (2KB/slot) -> deep prefetch with
//   zero register cost; all P reads are LDS. Partials via smem Pz.
// ---------------------------------------------------------------------------

#define BATCH       1024
#define MDIM        250
#define DTOT        500
#define HDIM        512
#define NITER       1000
#define NCHUNK      4
#define CHUNK       (NITER / NCHUNK)
#define ROWS_PER_CTA 8
#define SOLVER_CTAS (BATCH / ROWS_PER_CTA)
#define NTHR        512

#define OMEGA_F 1.8f
#define ALPHA_F (1.0f / 1.2f)

typedef unsigned long long ull;

#define FFMA2(d, a, b) \
    asm("fma.rn.f32x2 %0, %1, %2, %0;" : "+l"(d) : "l"(a), "l"(b))

__device__ __forceinline__ float2 f32x2_unpack(ull v) {
    float2 r;
    asm("mov.b64 {%0, %1}, %2;" : "=f"(r.x), "=f"(r.y) : "l"(v));
    return r;
}

__device__ __forceinline__ void cp_async16(unsigned sa, const void* g) {
    asm volatile("cp.async.cg.shared.global [%0], [%1], 16;" :: "r"(sa), "l"(g));
}
#define CP_COMMIT() asm volatile("cp.async.commit_group;")
#define CP_WAIT3()  asm volatile("cp.async.wait_group 3;")

// Scratch (device globals; zero-initialized, no runtime allocation)
__device__ float g_X1 [BATCH * HDIM];
__device__ float g_X2 [BATCH * HDIM];
__device__ float g_Ys [BATCH * DTOT];
__device__ float g_Q  [BATCH * DTOT];
__device__ float g_S  [BATCH * DTOT];
__device__ float g_P  [256 * 1024];     // 256 kp x (512 cols x 2); pad = 0

// ---------------------------------------------------------------------------
// Precompute GEMM (unchanged).
// ---------------------------------------------------------------------------
__device__ void gemm_dev(const float* __restrict__ A, const float* __restrict__ A2,
                         const float* __restrict__ B, const float* __restrict__ bias,
                         float* __restrict__ C,
                         int M, int N, int K, int mode, int bT, int aT)
{
    __shared__ float As[16][64];
    __shared__ float Bs[16][68];
    const int tid = threadIdx.x;
    const int tx = tid & 15, ty = tid >> 4;
    const int m0 = blockIdx.y * 64, n0 = blockIdx.x * 64;

    float acc[4][4];
    #pragma unroll
    for (int i = 0; i < 4; i++)
        #pragma unroll
        for (int j = 0; j < 4; j++) acc[i][j] = 0.f;

    for (int k0 = 0; k0 < K; k0 += 16) {
        #pragma unroll
        for (int i = 0; i < 4; i++) {
            int idx = tid + i * 256;
            int mr = idx >> 4, kk = idx & 15;
            int mg = m0 + mr, kg = k0 + kk;
            float av = 0.f;
            if (mg < M && kg < K) {
                if (aT)       av = A[(size_t)kg * M + mg];
                else if (A2)  av = (kg < MDIM) ? A[(size_t)mg * MDIM + kg]
                                               : A2[(size_t)mg * MDIM + (kg - MDIM)];
                else          av = A[(size_t)mg * K + kg];
            }
            As[kk][mr] = av;
        }
        #pragma unroll
        for (int i = 0; i < 4; i++) {
            int idx = tid + i * 256;
            if (!bT) {
                int kk = idx >> 6, cg = idx & 63;
                int kgl = k0 + kk, cgl = n0 + cg;
                Bs[kk][cg] = (kgl < K && cgl < N) ? B[(size_t)kgl * N + cgl] : 0.f;
            } else {
                int cg = idx >> 4, kk = idx & 15;
                int kgl = k0 + kk, cgl = n0 + cg;
                Bs[kk][cg] = (kgl < K && cgl < N) ? B[(size_t)cgl * K + kgl] : 0.f;
            }
        }
        __syncthreads();
        #pragma unroll
        for (int kk = 0; kk < 16; kk++) {
            float a[4], bb[4];
            #pragma unroll
            for (int i = 0; i < 4; i++) a[i] = As[kk][ty * 4 + i];
            #pragma unroll
            for (int j = 0; j < 4; j++) bb[j] = Bs[kk][tx * 4 + j];
            #pragma unroll
            for (int i = 0; i < 4; i++)
                #pragma unroll
                for (int j = 0; j < 4; j++) acc[i][j] += a[i] * bb[j];
        }
        __syncthreads();
    }

    #pragma unroll
    for (int i = 0; i < 4; i++) {
        int mg = m0 + ty * 4 + i;
        if (mg >= M) continue;
        #pragma unroll
        for (int j = 0; j < 4; j++) {
            int ng = n0 + tx * 4 + j;
            if (ng >= N) continue;
            float v = acc[i][j];
            if (bias) v += bias[ng];
            if (mode == 1)      v = fmaxf(v, 0.f);
            else if (mode == 2) v *= (1.0f / 6.0f);
            if (mode == 4) {
                v = ((mg == ng) ? 1.f : 0.f) - v;
                C[(size_t)(mg >> 1) * 1024 + ng * 2 + (mg & 1)] = v;
            } else {
                C[(size_t)mg * N + ng] = v;
            }
        }
    }
}

__global__ void gemm_kernel(const float* __restrict__ A, const float* __restrict__ A2,
                            const float* __restrict__ B, const float* __restrict__ bias,
                            float* __restrict__ C,
                            int M, int N, int K, int mode, int bT, int aT)
{
    gemm_dev(A, A2, B, bias, C, M, N, K, mode, bT, aT);
}

__global__ void precompute_fused(const float* b, const float* cin,
                                 const float* W1, const float* b1,
                                 const float* Aaug, const float* Ainv,
                                 float* X1, float* Q, float* P)
{
    int z = blockIdx.z;
    if (z == 0) {
        gemm_dev(b, cin, W1, b1, X1, BATCH, HDIM, DTOT, 1, 0, 0);
    } else if (z == 1) {
        gemm_dev(b, nullptr, Ainv, nullptr, Q, BATCH, DTOT, MDIM, 0, 1, 0);
    } else {
        if (blockIdx.y >= 8) return;
        gemm_dev(Aaug, nullptr, Ainv, nullptr, P, DTOT, DTOT, MDIM, 4, 1, 1);
    }
}

// ---------------------------------------------------------------------------
// Solver smem (floats):
//  Ssm[4096] | Pz[16384] | red[128] nrm[8] tls[8] pad->20736 |
//  ring[16 warps * 4 slots * 512] = 32768          total 53504 f = 214,016 B
// ---------------------------------------------------------------------------
#define SMEM_FLOATS 53504
#define SMEM_BYTES  (SMEM_FLOATS * 4)

__device__ __forceinline__ float soc_elem(float tp, int c, float nu, float tt)
{
    if (c < MDIM) return tp;
    if (nu <= tt) return tp;
    if (nu <= -tt) return 0.f;
    float h = 0.5f * (tt + nu);
    return (c == DTOT - 1) ? h : h * tp / (nu + 1e-12f);
}

// 8 FFMA2 for one 2-kp step, one row r.
#define ROW_STEP(r, sv, a0, a1, b0, b1)              \
    FFMA2(acc[r][0], (sv).x, (a0).x);                \
    FFMA2(acc[r][1], (sv).x, (a0).y);                \
    FFMA2(acc[r][2], (sv).x, (a1).x);                \
    FFMA2(acc[r][3], (sv).x, (a1).y);                \
    FFMA2(acc[r][0], (sv).y, (b0).x);                \
    FFMA2(acc[r][1], (sv).y, (b0).y);                \
    FFMA2(acc[r][2], (sv).y, (b1).x);                \
    FFMA2(acc[r][3], (sv).y, (b1).y)

// Issue the 4 cp.async (2 kp x 1KB) for step s into ring slot s&3.
__device__ __forceinline__ void issue_step(unsigned ring_sa, int s, int g, int cg, int lane)
{
    const int slot = s & 3;
    const float* src = g_P + (g * 64 + 2 * s) * 1024 + cg * 256 + lane * 4;
    unsigned dst = ring_sa + (unsigned)(slot * 2048 + lane * 16);
    cp_async16(dst,        src);               // kp even, bytes [0,512)
    cp_async16(dst + 512,  src + 128);         // kp even, bytes [512,1024)
    cp_async16(dst + 1024, src + 1024);        // kp odd,  bytes [0,512)
    cp_async16(dst + 1536, src + 1152);        // kp odd,  bytes [512,1024)
}

// Partial z over kgroup g's 128 k for this thread's 4 cols x 8 rows -> Pz.
__device__ __forceinline__ void gemm_partial(const float* __restrict__ Ssm,
                                             float* __restrict__ ringw,
                                             float* __restrict__ Pz,
                                             int g, int cg, int lane)
{
    unsigned ring_sa = (unsigned)__cvta_generic_to_shared(ringw);

    // prologue: 3 steps in flight
    #pragma unroll
    for (int d = 0; d < 3; d++) { issue_step(ring_sa, d, g, cg, lane); CP_COMMIT(); }

    ull acc[8][4];
    #pragma unroll
    for (int r = 0; r < 8; r++)
        #pragma unroll
        for (int j = 0; j < 4; j++) acc[r][j] = 0ull;

    #pragma unroll 4
    for (int s = 0; s < 32; s++) {
        if (s < 29) issue_step(ring_sa, s + 3, g, cg, lane);
        CP_COMMIT();                       // empty commits in tail keep count
        CP_WAIT3();                        // step s's group complete
        __syncwarp();

        const float* slotp = ringw + (s & 3) * 512 + lane * 8;
        ulonglong2 a0 = *reinterpret_cast<const ulonglong2*>(slotp);
        ulonglong2 a1 = *reinterpret_cast<const ulonglong2*>(slotp + 4);
        ulonglong2 b0 = *reinterpret_cast<const ulonglong2*>(slotp + 256);
        ulonglong2 b1 = *reinterpret_cast<const ulonglong2*>(slotp + 260);

        const int kf = g * 128 + 4 * s;    // float index of k base in S row
        #pragma unroll
        for (int r = 0; r < 8; r++) {
            ulonglong2 sv = *reinterpret_cast<const ulonglong2*>(&Ssm[r * 512 + kf]);
            ROW_STEP(r, sv, a0, a1, b0, b1);
        }
    }

    // reduce k-parity, store partials
    const int cbase = cg * 128 + lane * 4;
    float* dst = &Pz[g * 4096 + cbase];
    #pragma unroll
    for (int r = 0; r < 8; r++) {
        float2 u0 = f32x2_unpack(acc[r][0]);
        float2 u1 = f32x2_unpack(acc[r][1]);
        float2 u2 = f32x2_unpack(acc[r][2]);
        float2 u3 = f32x2_unpack(acc[r][3]);
        float2 v0; v0.x = u0.x + u0.y; v0.y = u1.x + u1.y;
        float2 v1; v1.x = u2.x + u2.y; v1.y = u3.x + u3.y;
        *reinterpret_cast<float2*>(&dst[r * 512])     = v0;
        *reinterpret_cast<float2*>(&dst[r * 512 + 2]) = v1;
    }
}

__global__ void __launch_bounds__(NTHR, 1) solver_kernel(float* __restrict__ out,
                                                         int start_it, int end_it)
{
    extern __shared__ float sm[];
    float* Ssm  = sm;              // 4096
    float* Pz   = sm + 4096;       // 16384
    float* red  = sm + 20480;      // 128
    float* nrm  = sm + 20608;      // 8
    float* tls  = sm + 20616;      // 8
    float* ring = sm + 20736;      // 16*2048

    const int t = threadIdx.x;
    const int w = t >> 5, lane = t & 31;
    const int g = w & 3, cg = w >> 2;
    float* ringw = ring + w * 2048;
    const int row0 = blockIdx.x * ROWS_PER_CTA;
    const int c = t;
    const bool act = (c < DTOT);

    // per-thread constants in registers
    float q[8], ys[8];
    #pragma unroll
    for (int r = 0; r < 8; r++) {
        if (act) {
            q[r]  = g_Q [(row0 + r) * DTOT + c];
            ys[r] = g_Ys[(row0 + r) * DTOT + c];
        } else { q[r] = 0.f; ys[r] = 0.f; }
    }

    // init S (strided, zero-padded)
    for (int i = t; i < ROWS_PER_CTA * 512; i += NTHR) {
        int r = i >> 9, cc = i & 511;
        float sv = 0.f;
        if (cc < DTOT && start_it != 0) sv = g_S[(row0 + r) * DTOT + cc];
        Ssm[i] = sv;
    }
    __syncthreads();

    for (int it = start_it; it < end_it; ++it) {
        gemm_partial(Ssm, ringw, Pz, g, cg, lane);
        __syncthreads();                               // B1: partials ready

        float z[8], tp[8], sold[8], val[8];
        const bool in_u = act && (c >= MDIM) && (c != DTOT - 1);
        #pragma unroll
        for (int r = 0; r < 8; r++) {
            if (act) {
                z[r] = Pz[r * 512 + c] + Pz[4096 + r * 512 + c]
                     + Pz[8192 + r * 512 + c] + Pz[12288 + r * 512 + c]
                     + q[r];
                sold[r] = Ssm[r * 512 + c];
                tp[r] = ALPHA_F * (2.f * z[r] - sold[r]) - ys[r];
                val[r] = in_u ? tp[r] * tp[r] : 0.f;
            } else { z[r] = 0.f; tp[r] = 0.f; sold[r] = 0.f; val[r] = 0.f; }
        }
        #pragma unroll
        for (int off = 16; off; off >>= 1)
            #pragma unroll
            for (int r = 0; r < 8; r++)
                val[r] += __shfl_down_sync(0xffffffffu, val[r], off);
        if (lane == 0) {
            #pragma unroll
            for (int r = 0; r < 8; r++) red[w * 8 + r] = val[r];
        }
        if (t == DTOT - 1) {
            #pragma unroll
            for (int r = 0; r < 8; r++) tls[r] = tp[r];
        }
        __syncthreads();                               // B2
        if (w < 8 && lane < 16) {                      // warp w reduces row w
            float s = red[lane * 8 + w];
            #pragma unroll
            for (int off = 8; off; off >>= 1)
                s += __shfl_down_sync(0x0000ffffu, s, off);
            if (lane == 0) nrm[w] = sqrtf(s);
        }
        __syncthreads();                               // B3
        if (act) {
            #pragma unroll
            for (int r = 0; r < 8; r++) {
                float tk = soc_elem(tp[r], c, nrm[r], tls[r]);
                Ssm[r * 512 + c] = sold[r] + OMEGA_F * (tk - z[r]);
            }
        }
        __syncthreads();                               // B4
    }

    if (end_it == NITER) {
        gemm_partial(Ssm, ringw, Pz, g, cg, lane);
        __syncthreads();
        if (act) {
            #pragma unroll
            for (int r = 0; r < 8; r++) {
                float zv = Pz[r * 512 + c] + Pz[4096 + r * 512 + c]
                         + Pz[8192 + r * 512 + c] + Pz[12288 + r * 512 + c]
                         + q[r];
                out[(row0 + r) * DTOT + c] = zv;
            }
        }
    } else if (act) {
        #pragma unroll
        for (int r = 0; r < 8; r++)
            g_S[(row0 + r) * DTOT + c] = Ssm[r * 512 + c];
    }
}

// ---------------------------------------------------------------------------
extern "C" void kernel_launch(void* const* d_in, const int* in_sizes, int n_in,
                              void* d_out, int out_size)
{
    const float* b    = (const float*)d_in[0];
    const float* cin  = (const float*)d_in[1];
    const float* W1   = (const float*)d_in[2];
    const float* b1   = (const float*)d_in[3];
    const float* W2   = (const float*)d_in[4];
    const float* b2   = (const float*)d_in[5];
    const float* W3   = (const float*)d_in[6];
    const float* b3   = (const float*)d_in[7];
    const float* Aaug = (const float*)d_in[8];
    const float* Ainv = (const float*)d_in[9];
    float* out = (float*)d_out;

    float *X1, *X2, *Ys, *Q, *P;
    cudaGetSymbolAddress((void**)&X1, g_X1);
    cudaGetSymbolAddress((void**)&X2, g_X2);
    cudaGetSymbolAddress((void**)&Ys, g_Ys);
    cudaGetSymbolAddress((void**)&Q,  g_Q);
    cudaGetSymbolAddress((void**)&P,  g_P);

    cudaFuncSetAttribute(solver_kernel,
                         cudaFuncAttributeMaxDynamicSharedMemorySize, SMEM_BYTES);

    precompute_fused<<<dim3(8, 16, 3), 256>>>(b, cin, W1, b1, Aaug, Ainv, X1, Q, P);
    gemm_kernel<<<dim3(8, 16), 256>>>(X1, nullptr, W2, b2, X2, BATCH, HDIM, HDIM, 1, 0, 0);
    gemm_kernel<<<dim3(8, 16), 256>>>(X2, nullptr, W3, b3, Ys, BATCH, DTOT, HDIM, 2, 0, 0);
    for (int ch = 0; ch < NCHUNK; ch++)
        solver_kernel<<<SOLVER_CTAS, NTHR, SMEM_BYTES>>>(out, ch * CHUNK, (ch + 1) * CHUNK);
}

// round 10
// speedup vs baseline: 1.7172x; 1.1053x over previous
#include <cuda_runtime.h>
#include <math.h>

// ---------------------------------------------------------------------------
// HardConstrainedMLP. proj_pinv(s) = s @ P + Q.
// Solver (per CTA: 8 batch rows, 512 threads, 16 warps):
//   warp w -> kgroup g = w&3 (128 k), colgroup cg = w>>2 (128 cols).
//   Thread lane owns cols {2l,2l+1,64+2l,64+2l+1} of its colgroup, 8 rows.
//   P (k-pair interleaved: g_P[kp*1024 + 2c + parity]) streamed via a
//   warp-private 4-slot cp.async ring; ring reads are lane*16B -> conflict-
//   free, and each lane reads only its own cp.async data (no syncwarp).
// ---------------------------------------------------------------------------

#define BATCH       1024
#define MDIM        250
#define DTOT        500
#define HDIM        512
#define NITER       1000
#define NCHUNK      4
#define CHUNK       (NITER / NCHUNK)
#define ROWS_PER_CTA 8
#define SOLVER_CTAS (BATCH / ROWS_PER_CTA)
#define NTHR        512

#define OMEGA_F 1.8f
#define ALPHA_F (1.0f / 1.2f)

typedef unsigned long long ull;

#define FFMA2(d, a, b) \
    asm("fma.rn.f32x2 %0, %1, %2, %0;" : "+l"(d) : "l"(a), "l"(b))

__device__ __forceinline__ float2 f32x2_unpack(ull v) {
    float2 r;
    asm("mov.b64 {%0, %1}, %2;" : "=f"(r.x), "=f"(r.y) : "l"(v));
    return r;
}

__device__ __forceinline__ void cp_async16(unsigned sa, const void* g) {
    asm volatile("cp.async.cg.shared.global [%0], [%1], 16;" :: "r"(sa), "l"(g));
}
#define CP_COMMIT() asm volatile("cp.async.commit_group;")
#define CP_WAIT3()  asm volatile("cp.async.wait_group 3;")

// Scratch (device globals; zero-initialized, no runtime allocation)
__device__ float g_X1 [BATCH * HDIM];
__device__ float g_X2 [BATCH * HDIM];
__device__ float g_Ys [BATCH * DTOT];
__device__ float g_Q  [BATCH * DTOT];
__device__ float g_S  [BATCH * DTOT];
__device__ float g_P  [256 * 1024];     // 256 kp x (512 cols x 2); pad = 0

// ---------------------------------------------------------------------------
// Precompute GEMM (unchanged).
// ---------------------------------------------------------------------------
__device__ void gemm_dev(const float* __restrict__ A, const float* __restrict__ A2,
                         const float* __restrict__ B, const float* __restrict__ bias,
                         float* __restrict__ C,
                         int M, int N, int K, int mode, int bT, int aT)
{
    __shared__ float As[16][64];
    __shared__ float Bs[16][68];
    const int tid = threadIdx.x;
    const int tx = tid & 15, ty = tid >> 4;
    const int m0 = blockIdx.y * 64, n0 = blockIdx.x * 64;

    float acc[4][4];
    #pragma unroll
    for (int i = 0; i < 4; i++)
        #pragma unroll
        for (int j = 0; j < 4; j++) acc[i][j] = 0.f;

    for (int k0 = 0; k0 < K; k0 += 16) {
        #pragma unroll
        for (int i = 0; i < 4; i++) {
            int idx = tid + i * 256;
            int mr = idx >> 4, kk = idx & 15;
            int mg = m0 + mr, kg = k0 + kk;
            float av = 0.f;
            if (mg < M && kg < K) {
                if (aT)       av = A[(size_t)kg * M + mg];
                else if (A2)  av = (kg < MDIM) ? A[(size_t)mg * MDIM + kg]
                                               : A2[(size_t)mg * MDIM + (kg - MDIM)];
                else          av = A[(size_t)mg * K + kg];
            }
            As[kk][mr] = av;
        }
        #pragma unroll
        for (int i = 0; i < 4; i++) {
            int idx = tid + i * 256;
            if (!bT) {
                int kk = idx >> 6, cg = idx & 63;
                int kgl = k0 + kk, cgl = n0 + cg;
                Bs[kk][cg] = (kgl < K && cgl < N) ? B[(size_t)kgl * N + cgl] : 0.f;
            } else {
                int cg = idx >> 4, kk = idx & 15;
                int kgl = k0 + kk, cgl = n0 + cg;
                Bs[kk][cg] = (kgl < K && cgl < N) ? B[(size_t)cgl * K + kgl] : 0.f;
            }
        }
        __syncthreads();
        #pragma unroll
        for (int kk = 0; kk < 16; kk++) {
            float a[4], bb[4];
            #pragma unroll
            for (int i = 0; i < 4; i++) a[i] = As[kk][ty * 4 + i];
            #pragma unroll
            for (int j = 0; j < 4; j++) bb[j] = Bs[kk][tx * 4 + j];
            #pragma unroll
            for (int i = 0; i < 4; i++)
                #pragma unroll
                for (int j = 0; j < 4; j++) acc[i][j] += a[i] * bb[j];
        }
        __syncthreads();
    }

    #pragma unroll
    for (int i = 0; i < 4; i++) {
        int mg = m0 + ty * 4 + i;
        if (mg >= M) continue;
        #pragma unroll
        for (int j = 0; j < 4; j++) {
            int ng = n0 + tx * 4 + j;
            if (ng >= N) continue;
            float v = acc[i][j];
            if (bias) v += bias[ng];
            if (mode == 1)      v = fmaxf(v, 0.f);
            else if (mode == 2) v *= (1.0f / 6.0f);
            if (mode == 4) {
                v = ((mg == ng) ? 1.f : 0.f) - v;
                C[(size_t)(mg >> 1) * 1024 + ng * 2 + (mg & 1)] = v;
            } else {
                C[(size_t)mg * N + ng] = v;
            }
        }
    }
}

__global__ void gemm_kernel(const float* __restrict__ A, const float* __restrict__ A2,
                            const float* __restrict__ B, const float* __restrict__ bias,
                            float* __restrict__ C,
                            int M, int N, int K, int mode, int bT, int aT)
{
    gemm_dev(A, A2, B, bias, C, M, N, K, mode, bT, aT);
}

__global__ void precompute_fused(const float* b, const float* cin,
                                 const float* W1, const float* b1,
                                 const float* Aaug, const float* Ainv,
                                 float* X1, float* Q, float* P)
{
    int z = blockIdx.z;
    if (z == 0) {
        gemm_dev(b, cin, W1, b1, X1, BATCH, HDIM, DTOT, 1, 0, 0);
    } else if (z == 1) {
        gemm_dev(b, nullptr, Ainv, nullptr, Q, BATCH, DTOT, MDIM, 0, 1, 0);
    } else {
        if (blockIdx.y >= 8) return;
        gemm_dev(Aaug, nullptr, Ainv, nullptr, P, DTOT, DTOT, MDIM, 4, 1, 1);
    }
}

// ---------------------------------------------------------------------------
// Solver smem (floats):
//  Ssm[4096] | Pz[16384] | red[128] nrm[8] tls[8] pad->20736 |
//  ring[16 warps * 4 slots * 512] = 32768          total 53504 f = 214,016 B
// ---------------------------------------------------------------------------
#define SMEM_FLOATS 53504
#define SMEM_BYTES  (SMEM_FLOATS * 4)

__device__ __forceinline__ float soc_elem(float tp, int c, float nu, float tt)
{
    if (c < MDIM) return tp;
    if (nu <= tt) return tp;
    if (nu <= -tt) return 0.f;
    float h = 0.5f * (tt + nu);
    return (c == DTOT - 1) ? h : h * tp / (nu + 1e-12f);
}

// 8 FFMA2 for one step, one row r.
// a0: even-kp cols (c0,c0+1) k-parity-packed; a1: even-kp cols (c1,c1+1);
// b0/b1: odd-kp same cols.  sv.x = S even-kp pair, sv.y = S odd-kp pair.
#define ROW_STEP(r, sv, a0, a1, b0, b1)              \
    FFMA2(acc[r][0], (sv).x, (a0).x);                \
    FFMA2(acc[r][1], (sv).x, (a0).y);                \
    FFMA2(acc[r][2], (sv).x, (a1).x);                \
    FFMA2(acc[r][3], (sv).x, (a1).y);                \
    FFMA2(acc[r][0], (sv).y, (b0).x);                \
    FFMA2(acc[r][1], (sv).y, (b0).y);                \
    FFMA2(acc[r][2], (sv).y, (b1).x);                \
    FFMA2(acc[r][3], (sv).y, (b1).y)

// Issue the 4 cp.async (2 kp x 1KB) for step s into ring slot s&3.
// chunk0: even kp, cols cg*128+[0,64) ; chunk1: even kp, +[64,128)
// chunk2: odd  kp, cols cg*128+[0,64) ; chunk3: odd  kp, +[64,128)
__device__ __forceinline__ void issue_step(unsigned ring_sa, int s, int g, int cg, int lane)
{
    const int slot = s & 3;
    const float* src = g_P + (g * 64 + 2 * s) * 1024 + cg * 256 + lane * 4;
    unsigned dst = ring_sa + (unsigned)(slot * 2048 + lane * 16);
    cp_async16(dst,        src);               // even kp, cols 2l,2l+1
    cp_async16(dst + 512,  src + 128);         // even kp, cols 64+2l,64+2l+1
    cp_async16(dst + 1024, src + 1024);        // odd kp,  cols 2l,2l+1
    cp_async16(dst + 1536, src + 1152);        // odd kp,  cols 64+2l,64+2l+1
}

// Partial z over kgroup g's 128 k for this thread's 4 cols x 8 rows -> Pz.
__device__ __forceinline__ void gemm_partial(const float* __restrict__ Ssm,
                                             float* __restrict__ ringw,
                                             float* __restrict__ Pz,
                                             int g, int cg, int lane)
{
    unsigned ring_sa = (unsigned)__cvta_generic_to_shared(ringw);

    // prologue: 3 steps in flight
    #pragma unroll
    for (int d = 0; d < 3; d++) { issue_step(ring_sa, d, g, cg, lane); CP_COMMIT(); }

    ull acc[8][4];
    #pragma unroll
    for (int r = 0; r < 8; r++)
        #pragma unroll
        for (int j = 0; j < 4; j++) acc[r][j] = 0ull;

    #pragma unroll 4
    for (int s = 0; s < 32; s++) {
        if (s < 29) issue_step(ring_sa, s + 3, g, cg, lane);
        CP_COMMIT();                       // empty commits in tail keep count
        CP_WAIT3();                        // step s's group complete
        // each lane reads only bytes its own cp.async wrote -> no syncwarp

        const float* slotp = ringw + (s & 3) * 512 + lane * 4;
        ulonglong2 a0 = *reinterpret_cast<const ulonglong2*>(slotp);         // even kp
        ulonglong2 a1 = *reinterpret_cast<const ulonglong2*>(slotp + 128);
        ulonglong2 b0 = *reinterpret_cast<const ulonglong2*>(slotp + 256);   // odd kp
        ulonglong2 b1 = *reinterpret_cast<const ulonglong2*>(slotp + 384);

        const int kf = g * 128 + 4 * s;    // float index of k base in S row
        #pragma unroll
        for (int r = 0; r < 8; r++) {
            ulonglong2 sv = *reinterpret_cast<const ulonglong2*>(&Ssm[r * 512 + kf]);
            ROW_STEP(r, sv, a0, a1, b0, b1);
        }
    }

    // reduce k-parity, store partials (cols 2l,2l+1 and 64+2l,64+2l+1)
    float* dst = &Pz[g * 4096 + cg * 128 + 2 * lane];
    #pragma unroll
    for (int r = 0; r < 8; r++) {
        float2 u0 = f32x2_unpack(acc[r][0]);
        float2 u1 = f32x2_unpack(acc[r][1]);
        float2 u2 = f32x2_unpack(acc[r][2]);
        float2 u3 = f32x2_unpack(acc[r][3]);
        float2 v0; v0.x = u0.x + u0.y; v0.y = u1.x + u1.y;
        float2 v1; v1.x = u2.x + u2.y; v1.y = u3.x + u3.y;
        *reinterpret_cast<float2*>(&dst[r * 512])      = v0;
        *reinterpret_cast<float2*>(&dst[r * 512 + 64]) = v1;
    }
}

__global__ void __launch_bounds__(NTHR, 1) solver_kernel(float* __restrict__ out,
                                                         int start_it, int end_it)
{
    extern __shared__ float sm[];
    float* Ssm  = sm;              // 4096
    float* Pz   = sm + 4096;       // 16384
    float* red  = sm + 20480;      // 128
    float* nrm  = sm + 20608;      // 8
    float* tls  = sm + 20616;      // 8
    float* ring = sm + 20736;      // 16*2048

    const int t = threadIdx.x;
    const int w = t >> 5, lane = t & 31;
    const int g = w & 3, cg = w >> 2;
    float* ringw = ring + w * 2048;
    const int row0 = blockIdx.x * ROWS_PER_CTA;
    const int c = t;
    const bool act = (c < DTOT);

    // per-thread constants in registers
    float q[8], ys[8];
    #pragma unroll
    for (int r = 0; r < 8; r++) {
        if (act) {
            q[r]  = g_Q [(row0 + r) * DTOT + c];
            ys[r] = g_Ys[(row0 + r) * DTOT + c];
        } else { q[r] = 0.f; ys[r] = 0.f; }
    }

    // init S (strided, zero-padded)
    for (int i = t; i < ROWS_PER_CTA * 512; i += NTHR) {
        int r = i >> 9, cc = i & 511;
        float sv = 0.f;
        if (cc < DTOT && start_it != 0) sv = g_S[(row0 + r) * DTOT + cc];
        Ssm[i] = sv;
    }
    __syncthreads();

    for (int it = start_it; it < end_it; ++it) {
        gemm_partial(Ssm, ringw, Pz, g, cg, lane);
        __syncthreads();                               // B1: partials ready

        float z[8], tp[8], sold[8], val[8];
        const bool in_u = act && (c >= MDIM) && (c != DTOT - 1);
        #pragma unroll
        for (int r = 0; r < 8; r++) {
            if (act) {
                z[r] = Pz[r * 512 + c] + Pz[4096 + r * 512 + c]
                     + Pz[8192 + r * 512 + c] + Pz[12288 + r * 512 + c]
                     + q[r];
                sold[r] = Ssm[r * 512 + c];
                tp[r] = ALPHA_F * (2.f * z[r] - sold[r]) - ys[r];
                val[r] = in_u ? tp[r] * tp[r] : 0.f;
            } else { z[r] = 0.f; tp[r] = 0.f; sold[r] = 0.f; val[r] = 0.f; }
        }
        #pragma unroll
        for (int off = 16; off; off >>= 1)
            #pragma unroll
            for (int r = 0; r < 8; r++)
                val[r] += __shfl_down_sync(0xffffffffu, val[r], off);
        if (lane == 0) {
            #pragma unroll
            for (int r = 0; r < 8; r++) red[w * 8 + r] = val[r];
        }
        if (t == DTOT - 1) {
            #pragma unroll
            for (int r = 0; r < 8; r++) tls[r] = tp[r];
        }
        __syncthreads();                               // B2
        if (w < 8 && lane < 16) {                      // warp w reduces row w
            float s = red[lane * 8 + w];
            #pragma unroll
            for (int off = 8; off; off >>= 1)
                s += __shfl_down_sync(0x0000ffffu, s, off);
            if (lane == 0) nrm[w] = sqrtf(s);
        }
        __syncthreads();                               // B3
        if (act) {
            #pragma unroll
            for (int r = 0; r < 8; r++) {
                float tk = soc_elem(tp[r], c, nrm[r], tls[r]);
                Ssm[r * 512 + c] = sold[r] + OMEGA_F * (tk - z[r]);
            }
        }
        __syncthreads();                               // B4
    }

    if (end_it == NITER) {
        gemm_partial(Ssm, ringw, Pz, g, cg, lane);
        __syncthreads();
        if (act) {
            #pragma unroll
            for (int r = 0; r < 8; r++) {
                float zv = Pz[r * 512 + c] + Pz[4096 + r * 512 + c]
                         + Pz[8192 + r * 512 + c] + Pz[12288 + r * 512 + c]
                         + q[r];
                out[(row0 + r) * DTOT + c] = zv;
            }
        }
    } else if (act) {
        #pragma unroll
        for (int r = 0; r < 8; r++)
            g_S[(row0 + r) * DTOT + c] = Ssm[r * 512 + c];
    }
}

// ---------------------------------------------------------------------------
extern "C" void kernel_launch(void* const* d_in, const int* in_sizes, int n_in,
                              void* d_out, int out_size)
{
    const float* b    = (const float*)d_in[0];
    const float* cin  = (const float*)d_in[1];
    const float* W1   = (const float*)d_in[2];
    const float* b1   = (const float*)d_in[3];
    const float* W2   = (const float*)d_in[4];
    const float* b2   = (const float*)d_in[5];
    const float* W3   = (const float*)d_in[6];
    const float* b3   = (const float*)d_in[7];
    const float* Aaug = (const float*)d_in[8];
    const float* Ainv = (const float*)d_in[9];
    float* out = (float*)d_out;

    float *X1, *X2, *Ys, *Q, *P;
    cudaGetSymbolAddress((void**)&X1, g_X1);
    cudaGetSymbolAddress((void**)&X2, g_X2);
    cudaGetSymbolAddress((void**)&Ys, g_Ys);
    cudaGetSymbolAddress((void**)&Q,  g_Q);
    cudaGetSymbolAddress((void**)&P,  g_P);

    cudaFuncSetAttribute(solver_kernel,
                         cudaFuncAttributeMaxDynamicSharedMemorySize, SMEM_BYTES);

    precompute_fused<<<dim3(8, 16, 3), 256>>>(b, cin, W1, b1, Aaug, Ainv, X1, Q, P);
    gemm_kernel<<<dim3(8, 16), 256>>>(X1, nullptr, W2, b2, X2, BATCH, HDIM, HDIM, 1, 0, 0);
    gemm_kernel<<<dim3(8, 16), 256>>>(X2, nullptr, W3, b3, Ys, BATCH, DTOT, HDIM, 2, 0, 0);
    for (int ch = 0; ch < NCHUNK; ch++)
        solver_kernel<<<SOLVER_CTAS, NTHR, SMEM_BYTES>>>(out, ch * CHUNK, (ch + 1) * CHUNK);
}

// round 11
// speedup vs baseline: 1.7195x; 1.0013x over previous
#include <cuda_runtime.h>
#include <math.h>

// ---------------------------------------------------------------------------
// HardConstrainedMLP. proj_pinv(s) = s @ P + Q.
// Solver (per CTA: 8 batch rows, 512 threads, 16 warps):
//   warp w -> kgroup g = w&3 (128 k), colgroup cg = w>>2 (128 cols).
//   Thread lane owns cols {2l,2l+1,64+2l,64+2l+1} of its colgroup, 8 rows.
//   P (k-pair interleaved: g_P[kp*1024 + 2c + parity]) streamed via a
//   warp-private 4-slot cp.async ring; ring reads are lane*16B -> conflict-
//   free, and each lane reads only its own cp.async data (no syncwarp).
// ---------------------------------------------------------------------------

#define BATCH       1024
#define MDIM        250
#define DTOT        500
#define HDIM        512
#define NITER       1000
#define NCHUNK      4
#define CHUNK       (NITER / NCHUNK)
#define ROWS_PER_CTA 8
#define SOLVER_CTAS (BATCH / ROWS_PER_CTA)
#define NTHR        512

#define OMEGA_F 1.8f
#define ALPHA_F (1.0f / 1.2f)

typedef unsigned long long ull;

#define FFMA2(d, a, b) \
    asm("fma.rn.f32x2 %0, %1, %2, %0;" : "+l"(d) : "l"(a), "l"(b))

__device__ __forceinline__ float2 f32x2_unpack(ull v) {
    float2 r;
    asm("mov.b64 {%0, %1}, %2;" : "=f"(r.x), "=f"(r.y) : "l"(v));
    return r;
}

__device__ __forceinline__ void cp_async16(unsigned sa, const void* g) {
    asm volatile("cp.async.cg.shared.global [%0], [%1], 16;" :: "r"(sa), "l"(g));
}
#define CP_COMMIT() asm volatile("cp.async.commit_group;")
#define CP_WAIT3()  asm volatile("cp.async.wait_group 3;")

// Scratch (device globals; zero-initialized, no runtime allocation)
__device__ float g_X1 [BATCH * HDIM];
__device__ float g_X2 [BATCH * HDIM];
__device__ float g_Ys [BATCH * DTOT];
__device__ float g_Q  [BATCH * DTOT];
__device__ float g_S  [BATCH * DTOT];
__device__ float g_P  [256 * 1024];     // 256 kp x (512 cols x 2); pad = 0

// ---------------------------------------------------------------------------
// Precompute GEMM (unchanged).
// ---------------------------------------------------------------------------
__device__ void gemm_dev(const float* __restrict__ A, const float* __restrict__ A2,
                         const float* __restrict__ B, const float* __restrict__ bias,
                         float* __restrict__ C,
                         int M, int N, int K, int mode, int bT, int aT)
{
    __shared__ float As[16][64];
    __shared__ float Bs[16][68];
    const int tid = threadIdx.x;
    const int tx = tid & 15, ty = tid >> 4;
    const int m0 = blockIdx.y * 64, n0 = blockIdx.x * 64;

    float acc[4][4];
    #pragma unroll
    for (int i = 0; i < 4; i++)
        #pragma unroll
        for (int j = 0; j < 4; j++) acc[i][j] = 0.f;

    for (int k0 = 0; k0 < K; k0 += 16) {
        #pragma unroll
        for (int i = 0; i < 4; i++) {
            int idx = tid + i * 256;
            int mr = idx >> 4, kk = idx & 15;
            int mg = m0 + mr, kg = k0 + kk;
            float av = 0.f;
            if (mg < M && kg < K) {
                if (aT)       av = A[(size_t)kg * M + mg];
                else if (A2)  av = (kg < MDIM) ? A[(size_t)mg * MDIM + kg]
                                               : A2[(size_t)mg * MDIM + (kg - MDIM)];
                else          av = A[(size_t)mg * K + kg];
            }
            As[kk][mr] = av;
        }
        #pragma unroll
        for (int i = 0; i < 4; i++) {
            int idx = tid + i * 256;
            if (!bT) {
                int kk = idx >> 6, cg = idx & 63;
                int kgl = k0 + kk, cgl = n0 + cg;
                Bs[kk][cg] = (kgl < K && cgl < N) ? B[(size_t)kgl * N + cgl] : 0.f;
            } else {
                int cg = idx >> 4, kk = idx & 15;
                int kgl = k0 + kk, cgl = n0 + cg;
                Bs[kk][cg] = (kgl < K && cgl < N) ? B[(size_t)cgl * K + kgl] : 0.f;
            }
        }
        __syncthreads();
        #pragma unroll
        for (int kk = 0; kk < 16; kk++) {
            float a[4], bb[4];
            #pragma unroll
            for (int i = 0; i < 4; i++) a[i] = As[kk][ty * 4 + i];
            #pragma unroll
            for (int j = 0; j < 4; j++) bb[j] = Bs[kk][tx * 4 + j];
            #pragma unroll
            for (int i = 0; i < 4; i++)
                #pragma unroll
                for (int j = 0; j < 4; j++) acc[i][j] += a[i] * bb[j];
        }
        __syncthreads();
    }

    #pragma unroll
    for (int i = 0; i < 4; i++) {
        int mg = m0 + ty * 4 + i;
        if (mg >= M) continue;
        #pragma unroll
        for (int j = 0; j < 4; j++) {
            int ng = n0 + tx * 4 + j;
            if (ng >= N) continue;
            float v = acc[i][j];
            if (bias) v += bias[ng];
            if (mode == 1)      v = fmaxf(v, 0.f);
            else if (mode == 2) v *= (1.0f / 6.0f);
            if (mode == 4) {
                v = ((mg == ng) ? 1.f : 0.f) - v;
                C[(size_t)(mg >> 1) * 1024 + ng * 2 + (mg & 1)] = v;
            } else {
                C[(size_t)mg * N + ng] = v;
            }
        }
    }
}

__global__ void gemm_kernel(const float* __restrict__ A, const float* __restrict__ A2,
                            const float* __restrict__ B, const float* __restrict__ bias,
                            float* __restrict__ C,
                            int M, int N, int K, int mode, int bT, int aT)
{
    gemm_dev(A, A2, B, bias, C, M, N, K, mode, bT, aT);
}

__global__ void precompute_fused(const float* b, const float* cin,
                                 const float* W1, const float* b1,
                                 const float* Aaug, const float* Ainv,
                                 float* X1, float* Q, float* P)
{
    int z = blockIdx.z;
    if (z == 0) {
        gemm_dev(b, cin, W1, b1, X1, BATCH, HDIM, DTOT, 1, 0, 0);
    } else if (z == 1) {
        gemm_dev(b, nullptr, Ainv, nullptr, Q, BATCH, DTOT, MDIM, 0, 1, 0);
    } else {
        if (blockIdx.y >= 8) return;
        gemm_dev(Aaug, nullptr, Ainv, nullptr, P, DTOT, DTOT, MDIM, 4, 1, 1);
    }
}

// ---------------------------------------------------------------------------
// Solver smem (floats):
//  Ssm[4096] | Pz[16384] | red[128] nrm[8] tls[8] pad->20736 |
//  ring[16 warps * 4 slots * 512] = 32768          total 53504 f = 214,016 B
// ---------------------------------------------------------------------------
#define SMEM_FLOATS 53504
#define SMEM_BYTES  (SMEM_FLOATS * 4)

__device__ __forceinline__ float soc_elem(float tp, int c, float nu, float tt)
{
    if (c < MDIM) return tp;
    if (nu <= tt) return tp;
    if (nu <= -tt) return 0.f;
    float h = 0.5f * (tt + nu);
    return (c == DTOT - 1) ? h : h * tp / (nu + 1e-12f);
}

// 8 FFMA2 for one step, one row r.
// a0: even-kp cols (c0,c0+1) k-parity-packed; a1: even-kp cols (c1,c1+1);
// b0/b1: odd-kp same cols.  sv.x = S even-kp pair, sv.y = S odd-kp pair.
#define ROW_STEP(r, sv, a0, a1, b0, b1)              \
    FFMA2(acc[r][0], (sv).x, (a0).x);                \
    FFMA2(acc[r][1], (sv).x, (a0).y);                \
    FFMA2(acc[r][2], (sv).x, (a1).x);                \
    FFMA2(acc[r][3], (sv).x, (a1).y);                \
    FFMA2(acc[r][0], (sv).y, (b0).x);                \
    FFMA2(acc[r][1], (sv).y, (b0).y);                \
    FFMA2(acc[r][2], (sv).y, (b1).x);                \
    FFMA2(acc[r][3], (sv).y, (b1).y)

// Issue the 4 cp.async (2 kp x 1KB) for step s into ring slot s&3.
// chunk0: even kp, cols cg*128+[0,64) ; chunk1: even kp, +[64,128)
// chunk2: odd  kp, cols cg*128+[0,64) ; chunk3: odd  kp, +[64,128)
__device__ __forceinline__ void issue_step(unsigned ring_sa, int s, int g, int cg, int lane)
{
    const int slot = s & 3;
    const float* src = g_P + (g * 64 + 2 * s) * 1024 + cg * 256 + lane * 4;
    unsigned dst = ring_sa + (unsigned)(slot * 2048 + lane * 16);
    cp_async16(dst,        src);               // even kp, cols 2l,2l+1
    cp_async16(dst + 512,  src + 128);         // even kp, cols 64+2l,64+2l+1
    cp_async16(dst + 1024, src + 1024);        // odd kp,  cols 2l,2l+1
    cp_async16(dst + 1536, src + 1152);        // odd kp,  cols 64+2l,64+2l+1
}

// Partial z over kgroup g's 128 k for this thread's 4 cols x 8 rows -> Pz.
__device__ __forceinline__ void gemm_partial(const float* __restrict__ Ssm,
                                             float* __restrict__ ringw,
                                             float* __restrict__ Pz,
                                             int g, int cg, int lane)
{
    unsigned ring_sa = (unsigned)__cvta_generic_to_shared(ringw);

    // prologue: 3 steps in flight
    #pragma unroll
    for (int d = 0; d < 3; d++) { issue_step(ring_sa, d, g, cg, lane); CP_COMMIT(); }

    ull acc[8][4];
    #pragma unroll
    for (int r = 0; r < 8; r++)
        #pragma unroll
        for (int j = 0; j < 4; j++) acc[r][j] = 0ull;

    #pragma unroll 4
    for (int s = 0; s < 32; s++) {
        if (s < 29) issue_step(ring_sa, s + 3, g, cg, lane);
        CP_COMMIT();                       // empty commits in tail keep count
        CP_WAIT3();                        // step s's group complete
        // each lane reads only bytes its own cp.async wrote -> no syncwarp

        const float* slotp = ringw + (s & 3) * 512 + lane * 4;
        ulonglong2 a0 = *reinterpret_cast<const ulonglong2*>(slotp);         // even kp
        ulonglong2 a1 = *reinterpret_cast<const ulonglong2*>(slotp + 128);
        ulonglong2 b0 = *reinterpret_cast<const ulonglong2*>(slotp + 256);   // odd kp
        ulonglong2 b1 = *reinterpret_cast<const ulonglong2*>(slotp + 384);

        const int kf = g * 128 + 4 * s;    // float index of k base in S row
        #pragma unroll
        for (int r = 0; r < 8; r++) {
            ulonglong2 sv = *reinterpret_cast<const ulonglong2*>(&Ssm[r * 512 + kf]);
            ROW_STEP(r, sv, a0, a1, b0, b1);
        }
    }

    // reduce k-parity, store partials (cols 2l,2l+1 and 64+2l,64+2l+1)
    float* dst = &Pz[g * 4096 + cg * 128 + 2 * lane];
    #pragma unroll
    for (int r = 0; r < 8; r++) {
        float2 u0 = f32x2_unpack(acc[r][0]);
        float2 u1 = f32x2_unpack(acc[r][1]);
        float2 u2 = f32x2_unpack(acc[r][2]);
        float2 u3 = f32x2_unpack(acc[r][3]);
        float2 v0; v0.x = u0.x + u0.y; v0.y = u1.x + u1.y;
        float2 v1; v1.x = u2.x + u2.y; v1.y = u3.x + u3.y;
        *reinterpret_cast<float2*>(&dst[r * 512])      = v0;
        *reinterpret_cast<float2*>(&dst[r * 512 + 64]) = v1;
    }
}

__global__ void __launch_bounds__(NTHR, 1) solver_kernel(float* __restrict__ out,
                                                         int start_it, int end_it)
{
    extern __shared__ float sm[];
    float* Ssm  = sm;              // 4096
    float* Pz   = sm + 4096;       // 16384
    float* red  = sm + 20480;      // 128
    float* nrm  = sm + 20608;      // 8
    float* tls  = sm + 20616;      // 8
    float* ring = sm + 20736;      // 16*2048

    const int t = threadIdx.x;
    const int w = t >> 5, lane = t & 31;
    const int g = w & 3, cg = w >> 2;
    float* ringw = ring + w * 2048;
    const int row0 = blockIdx.x * ROWS_PER_CTA;
    const int c = t;
    const bool act = (c < DTOT);

    // per-thread constants in registers
    float q[8], ys[8];
    #pragma unroll
    for (int r = 0; r < 8; r++) {
        if (act) {
            q[r]  = g_Q [(row0 + r) * DTOT + c];
            ys[r] = g_Ys[(row0 + r) * DTOT + c];
        } else { q[r] = 0.f; ys[r] = 0.f; }
    }

    // init S (strided, zero-padded)
    for (int i = t; i < ROWS_PER_CTA * 512; i += NTHR) {
        int r = i >> 9, cc = i & 511;
        float sv = 0.f;
        if (cc < DTOT && start_it != 0) sv = g_S[(row0 + r) * DTOT + cc];
        Ssm[i] = sv;
    }
    __syncthreads();

    for (int it = start_it; it < end_it; ++it) {
        gemm_partial(Ssm, ringw, Pz, g, cg, lane);
        __syncthreads();                               // B1: partials ready

        float z[8], tp[8], sold[8], val[8];
        const bool in_u = act && (c >= MDIM) && (c != DTOT - 1);
        #pragma unroll
        for (int r = 0; r < 8; r++) {
            if (act) {
                z[r] = Pz[r * 512 + c] + Pz[4096 + r * 512 + c]
                     + Pz[8192 + r * 512 + c] + Pz[12288 + r * 512 + c]
                     + q[r];
                sold[r] = Ssm[r * 512 + c];
                tp[r] = ALPHA_F * (2.f * z[r] - sold[r]) - ys[r];
                val[r] = in_u ? tp[r] * tp[r] : 0.f;
            } else { z[r] = 0.f; tp[r] = 0.f; sold[r] = 0.f; val[r] = 0.f; }
        }
        #pragma unroll
        for (int off = 16; off; off >>= 1)
            #pragma unroll
            for (int r = 0; r < 8; r++)
                val[r] += __shfl_down_sync(0xffffffffu, val[r], off);
        if (lane == 0) {
            #pragma unroll
            for (int r = 0; r < 8; r++) red[w * 8 + r] = val[r];
        }
        if (t == DTOT - 1) {
            #pragma unroll
            for (int r = 0; r < 8; r++) tls[r] = tp[r];
        }
        __syncthreads();                               // B2
        if (w < 8 && lane < 16) {                      // warp w reduces row w
            float s = red[lane * 8 + w];
            #pragma unroll
            for (int off = 8; off; off >>= 1)
                s += __shfl_down_sync(0x0000ffffu, s, off);
            if (lane == 0) nrm[w] = sqrtf(s);
        }
        __syncthreads();                               // B3
        if (act) {
            #pragma unroll
            for (int r = 0; r < 8; r++) {
                float tk = soc_elem(tp[r], c, nrm[r], tls[r]);
                Ssm[r * 512 + c] = sold[r] + OMEGA_F * (tk - z[r]);
            }
        }
        __syncthreads();                               // B4
    }

    if (end_it == NITER) {
        gemm_partial(Ssm, ringw, Pz, g, cg, lane);
        __syncthreads();
        if (act) {
            #pragma unroll
            for (int r = 0; r < 8; r++) {
                float zv = Pz[r * 512 + c] + Pz[4096 + r * 512 + c]
                         + Pz[8192 + r * 512 + c] + Pz[12288 + r * 512 + c]
                         + q[r];
                out[(row0 + r) * DTOT + c] = zv;
            }
        }
    } else if (act) {
        #pragma unroll
        for (int r = 0; r < 8; r++)
            g_S[(row0 + r) * DTOT + c] = Ssm[r * 512 + c];
    }
}

// ---------------------------------------------------------------------------
extern "C" void kernel_launch(void* const* d_in, const int* in_sizes, int n_in,
                              void* d_out, int out_size)
{
    const float* b    = (const float*)d_in[0];
    const float* cin  = (const float*)d_in[1];
    const float* W1   = (const float*)d_in[2];
    const float* b1   = (const float*)d_in[3];
    const float* W2   = (const float*)d_in[4];
    const float* b2   = (const float*)d_in[5];
    const float* W3   = (const float*)d_in[6];
    const float* b3   = (const float*)d_in[7];
    const float* Aaug = (const float*)d_in[8];
    const float* Ainv = (const float*)d_in[9];
    float* out = (float*)d_out;

    float *X1, *X2, *Ys, *Q, *P;
    cudaGetSymbolAddress((void**)&X1, g_X1);
    cudaGetSymbolAddress((void**)&X2, g_X2);
    cudaGetSymbolAddress((void**)&Ys, g_Ys);
    cudaGetSymbolAddress((void**)&Q,  g_Q);
    cudaGetSymbolAddress((void**)&P,  g_P);

    cudaFuncSetAttribute(solver_kernel,
                         cudaFuncAttributeMaxDynamicSharedMemorySize, SMEM_BYTES);

    precompute_fused<<<dim3(8, 16, 3), 256>>>(b, cin, W1, b1, Aaug, Ainv, X1, Q, P);
    gemm_kernel<<<dim3(8, 16), 256>>>(X1, nullptr, W2, b2, X2, BATCH, HDIM, HDIM, 1, 0, 0);
    gemm_kernel<<<dim3(8, 16), 256>>>(X2, nullptr, W3, b3, Ys, BATCH, DTOT, HDIM, 2, 0, 0);
    for (int ch = 0; ch < NCHUNK; ch++)
        solver_kernel<<<SOLVER_CTAS, NTHR, SMEM_BYTES>>>(out, ch * CHUNK, (ch + 1) * CHUNK);
}

// round 12
// speedup vs baseline: 2.8614x; 1.6640x over previous
#include <cuda_runtime.h>
#include <math.h>

// ---------------------------------------------------------------------------
// HardConstrainedMLP. proj_pinv(s) = s @ P + Q,  P = I - Aaug^T Ainv^T.
// KEY ALGEBRA: P is idempotent (P^2 = P) and Q P = 0  =>  z P = z - Q, and
//   z_{k+1} = 0.7 z_k + C0 + 1.8 * (delta_k[250:] @ P[250:,:])
// where delta_k = tk - toproj (nonzero only on SOC cols 250..499) and
//   C0 = 0.3 Q - 1.8 (Ys @ P)   (precomputed once).
// => per-iteration GEMM halves: 250 k-rows instead of 500. s and z live in
// registers; only delta goes through smem. P2 = P[250:,:] streamed via
// warp-private cp.async ring (conflict-free, own-lane reads).
// Warp layout (16 warps): g = w&1 (64 kp of 128), cg = w>>1 (64 cols of 512).
// ---------------------------------------------------------------------------

#define BATCH       1024
#define MDIM        250
#define DTOT        500
#define HDIM        512
#define NITER       1000
#define NCHUNK      4
#define CHUNK       (NITER / NCHUNK)
#define ROWS_PER_CTA 8
#define SOLVER_CTAS (BATCH / ROWS_PER_CTA)
#define NTHR        512
#define KPG         64          // k-pairs per kgroup (2 groups x 64 = 128 kp)
#define NSTEPS      16          // 4 kp per step

#define OMEGA_F 1.8f
#define ALPHA_F (1.0f / 1.2f)

typedef unsigned long long ull;

#define FFMA2(d, a, b) \
    asm("fma.rn.f32x2 %0, %1, %2, %0;" : "+l"(d) : "l"(a), "l"(b))

__device__ __forceinline__ float2 f32x2_unpack(ull v) {
    float2 r;
    asm("mov.b64 {%0, %1}, %2;" : "=f"(r.x), "=f"(r.y) : "l"(v));
    return r;
}

__device__ __forceinline__ void cp_async16(unsigned sa, const void* g) {
    asm volatile("cp.async.cg.shared.global [%0], [%1], 16;" :: "r"(sa), "l"(g));
}
#define CP_COMMIT() asm volatile("cp.async.commit_group;")
#define CP_WAIT3()  asm volatile("cp.async.wait_group 3;")

// Scratch (device globals; zero-initialized, no runtime allocation)
__device__ float g_X1 [BATCH * HDIM];
__device__ float g_X2 [BATCH * HDIM];
__device__ float g_Ys [BATCH * DTOT];
__device__ float g_Q  [BATCH * DTOT];
__device__ float g_C0 [BATCH * DTOT];      // 0.3 Q - 1.8 Ys@P
__device__ float g_S  [BATCH * DTOT];
__device__ float g_Z  [BATCH * DTOT];
__device__ float g_Pn [DTOT * DTOT];       // P, plain row-major (for Ys@P)
__device__ float g_P2 [128 * 1024];        // P[250:,:], k-pair interleaved:
                                           // [kp*1024 + 2c + par], k=250+2kp+par

// ---------------------------------------------------------------------------
// Precompute GEMM.
//  mode: 1 relu, 2 *(1/6), 4 P dual-store (E=plain, C=interleaved rows>=250),
//        5 C0 = 0.3*E - 1.8*acc
// ---------------------------------------------------------------------------
__device__ void gemm_dev(const float* __restrict__ A, const float* __restrict__ A2,
                         const float* __restrict__ B, const float* __restrict__ bias,
                         float* __restrict__ C, float* __restrict__ E,
                         int M, int N, int K, int mode, int bT, int aT)
{
    __shared__ float As[16][64];
    __shared__ float Bs[16][68];
    const int tid = threadIdx.x;
    const int tx = tid & 15, ty = tid >> 4;
    const int m0 = blockIdx.y * 64, n0 = blockIdx.x * 64;

    float acc[4][4];
    #pragma unroll
    for (int i = 0; i < 4; i++)
        #pragma unroll
        for (int j = 0; j < 4; j++) acc[i][j] = 0.f;

    for (int k0 = 0; k0 < K; k0 += 16) {
        #pragma unroll
        for (int i = 0; i < 4; i++) {
            int idx = tid + i * 256;
            int mr = idx >> 4, kk = idx & 15;
            int mg = m0 + mr, kg = k0 + kk;
            float av = 0.f;
            if (mg < M && kg < K) {
                if (aT)       av = A[(size_t)kg * M + mg];
                else if (A2)  av = (kg < MDIM) ? A[(size_t)mg * MDIM + kg]
                                               : A2[(size_t)mg * MDIM + (kg - MDIM)];
                else          av = A[(size_t)mg * K + kg];
            }
            As[kk][mr] = av;
        }
        #pragma unroll
        for (int i = 0; i < 4; i++) {
            int idx = tid + i * 256;
            if (!bT) {
                int kk = idx >> 6, cg = idx & 63;
                int kgl = k0 + kk, cgl = n0 + cg;
                Bs[kk][cg] = (kgl < K && cgl < N) ? B[(size_t)kgl * N + cgl] : 0.f;
            } else {
                int cg = idx >> 4, kk = idx & 15;
                int kgl = k0 + kk, cgl = n0 + cg;
                Bs[kk][cg] = (kgl < K && cgl < N) ? B[(size_t)cgl * K + kgl] : 0.f;
            }
        }
        __syncthreads();
        #pragma unroll
        for (int kk = 0; kk < 16; kk++) {
            float a[4], bb[4];
            #pragma unroll
            for (int i = 0; i < 4; i++) a[i] = As[kk][ty * 4 + i];
            #pragma unroll
            for (int j = 0; j < 4; j++) bb[j] = Bs[kk][tx * 4 + j];
            #pragma unroll
            for (int i = 0; i < 4; i++)
                #pragma unroll
                for (int j = 0; j < 4; j++) acc[i][j] += a[i] * bb[j];
        }
        __syncthreads();
    }

    #pragma unroll
    for (int i = 0; i < 4; i++) {
        int mg = m0 + ty * 4 + i;
        if (mg >= M) continue;
        #pragma unroll
        for (int j = 0; j < 4; j++) {
            int ng = n0 + tx * 4 + j;
            if (ng >= N) continue;
            float v = acc[i][j];
            if (bias) v += bias[ng];
            if (mode == 1)      v = fmaxf(v, 0.f);
            else if (mode == 2) v *= (1.0f / 6.0f);
            if (mode == 4) {
                v = ((mg == ng) ? 1.f : 0.f) - v;
                E[(size_t)mg * DTOT + ng] = v;
                if (mg >= MDIM)
                    C[(size_t)((mg - MDIM) >> 1) * 1024 + ng * 2 + ((mg - MDIM) & 1)] = v;
            } else if (mode == 5) {
                C[(size_t)mg * N + ng] = 0.3f * E[(size_t)mg * N + ng] - 1.8f * v;
            } else {
                C[(size_t)mg * N + ng] = v;
            }
        }
    }
}

__global__ void gemm_kernel(const float* __restrict__ A, const float* __restrict__ A2,
                            const float* __restrict__ B, const float* __restrict__ bias,
                            float* __restrict__ C, float* __restrict__ E,
                            int M, int N, int K, int mode, int bT, int aT)
{
    gemm_dev(A, A2, B, bias, C, E, M, N, K, mode, bT, aT);
}

__global__ void precompute_fused(const float* b, const float* cin,
                                 const float* W1, const float* b1,
                                 const float* Aaug, const float* Ainv,
                                 float* X1, float* Q, float* P2, float* Pn)
{
    int z = blockIdx.z;
    if (z == 0) {
        gemm_dev(b, cin, W1, b1, X1, nullptr, BATCH, HDIM, DTOT, 1, 0, 0);
    } else if (z == 1) {
        gemm_dev(b, nullptr, Ainv, nullptr, Q, nullptr, BATCH, DTOT, MDIM, 0, 1, 0);
    } else {
        if (blockIdx.y >= 8) return;
        gemm_dev(Aaug, nullptr, Ainv, nullptr, P2, Pn, DTOT, DTOT, MDIM, 4, 1, 1);
    }
}

// ---------------------------------------------------------------------------
// Solver smem (floats):
//  Dsm[8*256]=2048 | Pz[2*8*512]=8192 | red[128] nrm[8] tls[8] pad->10496 |
//  ring[16 warps * 4 slots * 512] = 32768        total 43264 f = 173,056 B
// ---------------------------------------------------------------------------
#define SMEM_FLOATS 43264
#define SMEM_BYTES  (SMEM_FLOATS * 4)

__device__ __forceinline__ float soc_elem(float tp, int c, float nu, float tt)
{
    if (c < MDIM) return tp;
    if (nu <= tt) return tp;
    if (nu <= -tt) return 0.f;
    float h = 0.5f * (tt + nu);
    return (c == DTOT - 1) ? h : h * tp / (nu + 1e-12f);
}

// Issue 4 cp.async (4 kp x 512B: warp's 64-col slice) for step st.
__device__ __forceinline__ void issue_step(unsigned ring_sa, int st, int g, int cg, int lane)
{
    const int slot = st & 3;
    const float* src = g_P2 + (g * KPG + 4 * st) * 1024 + cg * 128 + lane * 4;
    unsigned dst = ring_sa + (unsigned)(slot * 2048 + lane * 16);
    cp_async16(dst,        src);               // kp+0
    cp_async16(dst + 512,  src + 1024);        // kp+1
    cp_async16(dst + 1024, src + 2048);        // kp+2
    cp_async16(dst + 1536, src + 3072);        // kp+3
}

// Partial w = delta @ P2 over kgroup g (64 kp) for 2 cols x 8 rows -> Pz.
__device__ __forceinline__ void gemm_partial(const float* __restrict__ Dsm,
                                             float* __restrict__ ringw,
                                             float* __restrict__ Pz,
                                             int g, int cg, int lane)
{
    unsigned ring_sa = (unsigned)__cvta_generic_to_shared(ringw);

    #pragma unroll
    for (int d = 0; d < 3; d++) { issue_step(ring_sa, d, g, cg, lane); CP_COMMIT(); }

    ull acc[8][2];
    #pragma unroll
    for (int r = 0; r < 8; r++) { acc[r][0] = 0ull; acc[r][1] = 0ull; }

    #pragma unroll 4
    for (int st = 0; st < NSTEPS; st++) {
        if (st < NSTEPS - 3) issue_step(ring_sa, st + 3, g, cg, lane);
        CP_COMMIT();
        CP_WAIT3();
        // own-lane reads only; no syncwarp needed

        const float* slotp = ringw + (st & 3) * 512 + lane * 4;
        ulonglong2 p0 = *reinterpret_cast<const ulonglong2*>(slotp);        // kp+0
        ulonglong2 p1 = *reinterpret_cast<const ulonglong2*>(slotp + 128);  // kp+1
        ulonglong2 p2 = *reinterpret_cast<const ulonglong2*>(slotp + 256);  // kp+2
        ulonglong2 p3 = *reinterpret_cast<const ulonglong2*>(slotp + 384);  // kp+3
        // p?.x = (par0,par1) for col c0 ; p?.y = for col c1

        const int kf = g * 128 + 8 * st;       // local-k float base in delta row
        #pragma unroll
        for (int r = 0; r < 8; r++) {
            ulonglong2 sa = *reinterpret_cast<const ulonglong2*>(&Dsm[r * 256 + kf]);
            ulonglong2 sb = *reinterpret_cast<const ulonglong2*>(&Dsm[r * 256 + kf + 4]);
            FFMA2(acc[r][0], sa.x, p0.x);  FFMA2(acc[r][1], sa.x, p0.y);
            FFMA2(acc[r][0], sa.y, p1.x);  FFMA2(acc[r][1], sa.y, p1.y);
            FFMA2(acc[r][0], sb.x, p2.x);  FFMA2(acc[r][1], sb.x, p2.y);
            FFMA2(acc[r][0], sb.y, p3.x);  FFMA2(acc[r][1], sb.y, p3.y);
        }
    }

    float* dst = &Pz[g * 4096 + cg * 64 + 2 * lane];
    #pragma unroll
    for (int r = 0; r < 8; r++) {
        float2 u0 = f32x2_unpack(acc[r][0]);
        float2 u1 = f32x2_unpack(acc[r][1]);
        float2 v; v.x = u0.x + u0.y; v.y = u1.x + u1.y;
        *reinterpret_cast<float2*>(&dst[r * 512]) = v;
    }
}

__global__ void __launch_bounds__(NTHR, 1) solver_kernel(float* __restrict__ out,
                                                         int start_it, int end_it)
{
    extern __shared__ float sm[];
    float* Dsm  = sm;              // 2048 (8 rows x 256 local-k, zero-padded)
    float* Pz   = sm + 2048;       // 8192 (2 groups x 8 x 512)
    float* red  = sm + 10240;      // 128
    float* nrm  = sm + 10368;      // 8
    float* tls  = sm + 10376;      // 8
    float* ring = sm + 10496;      // 16*2048

    const int t = threadIdx.x;
    const int w = t >> 5, lane = t & 31;
    const int g = w & 1, cg = w >> 1;
    float* ringw = ring + w * 2048;
    const int row0 = blockIdx.x * ROWS_PER_CTA;
    const int c = t;
    const bool act = (c < DTOT);

    // persistent per-thread state: s, z + constants ys, c0
    float s[8], z[8], ys[8], c0[8];
    #pragma unroll
    for (int r = 0; r < 8; r++) {
        if (act) {
            int idx = (row0 + r) * DTOT + c;
            ys[r] = g_Ys[idx];
            c0[r] = g_C0[idx];
            if (start_it == 0) { s[r] = 0.f; z[r] = g_Q[idx]; }
            else               { s[r] = g_S[idx]; z[r] = g_Z[idx]; }
        } else { s[r] = 0.f; z[r] = 0.f; ys[r] = 0.f; c0[r] = 0.f; }
    }

    // Dsm zero (pads stay zero forever; delta writes only local j < 250)
    for (int i = t; i < ROWS_PER_CTA * 256; i += NTHR) Dsm[i] = 0.f;
    __syncthreads();

    const bool in_u = act && (c >= MDIM) && (c != DTOT - 1);

    for (int it = start_it; it < end_it; ++it) {
        // ---- elementwise: toproj + ssq partials ----
        float tp[8], val[8];
        #pragma unroll
        for (int r = 0; r < 8; r++) {
            tp[r]  = act ? (ALPHA_F * (2.f * z[r] - s[r]) - ys[r]) : 0.f;
            val[r] = in_u ? tp[r] * tp[r] : 0.f;
        }
        #pragma unroll
        for (int off = 16; off; off >>= 1)
            #pragma unroll
            for (int r = 0; r < 8; r++)
                val[r] += __shfl_down_sync(0xffffffffu, val[r], off);
        if (lane == 0) {
            #pragma unroll
            for (int r = 0; r < 8; r++) red[w * 8 + r] = val[r];
        }
        if (t == DTOT - 1) {
            #pragma unroll
            for (int r = 0; r < 8; r++) tls[r] = tp[r];
        }
        __syncthreads();                               // B1
        if (w < 8 && lane < 16) {                      // warp w reduces row w
            float sv = red[lane * 8 + w];
            #pragma unroll
            for (int off = 8; off; off >>= 1)
                sv += __shfl_down_sync(0x0000ffffu, sv, off);
            if (lane == 0) nrm[w] = sqrtf(sv);
        }
        __syncthreads();                               // B2
        // ---- tk, delta, s-update ----
        if (act) {
            #pragma unroll
            for (int r = 0; r < 8; r++) {
                float tk = soc_elem(tp[r], c, nrm[r], tls[r]);
                s[r] += OMEGA_F * (tk - z[r]);
                if (c >= MDIM) Dsm[r * 256 + (c - MDIM)] = tk - tp[r];
            }
        }
        __syncthreads();                               // B3: delta visible
        gemm_partial(Dsm, ringw, Pz, g, cg, lane);
        __syncthreads();                               // B4: partials ready
        // ---- z-recursion: z = 0.7 z + C0 + 1.8 (delta @ P2) ----
        if (act) {
            #pragma unroll
            for (int r = 0; r < 8; r++) {
                float wv = Pz[r * 512 + c] + Pz[4096 + r * 512 + c];
                z[r] = 0.7f * z[r] + c0[r] + 1.8f * wv;
            }
        }
        // no barrier needed: Pz next written after B3' of next iteration
    }

    if (end_it == NITER) {
        if (act) {
            #pragma unroll
            for (int r = 0; r < 8; r++)
                out[(row0 + r) * DTOT + c] = z[r];     // z_K = proj_pinv(s_K)
        }
    } else if (act) {
        #pragma unroll
        for (int r = 0; r < 8; r++) {
            int idx = (row0 + r) * DTOT + c;
            g_S[idx] = s[r];
            g_Z[idx] = z[r];
        }
    }
}

// ---------------------------------------------------------------------------
extern "C" void kernel_launch(void* const* d_in, const int* in_sizes, int n_in,
                              void* d_out, int out_size)
{
    const float* b    = (const float*)d_in[0];
    const float* cin  = (const float*)d_in[1];
    const float* W1   = (const float*)d_in[2];
    const float* b1   = (const float*)d_in[3];
    const float* W2   = (const float*)d_in[4];
    const float* b2   = (const float*)d_in[5];
    const float* W3   = (const float*)d_in[6];
    const float* b3   = (const float*)d_in[7];
    const float* Aaug = (const float*)d_in[8];
    const float* Ainv = (const float*)d_in[9];
    float* out = (float*)d_out;

    float *X1, *X2, *Ys, *Q, *C0, *Pn, *P2;
    cudaGetSymbolAddress((void**)&X1, g_X1);
    cudaGetSymbolAddress((void**)&X2, g_X2);
    cudaGetSymbolAddress((void**)&Ys, g_Ys);
    cudaGetSymbolAddress((void**)&Q,  g_Q);
    cudaGetSymbolAddress((void**)&C0, g_C0);
    cudaGetSymbolAddress((void**)&Pn, g_Pn);
    cudaGetSymbolAddress((void**)&P2, g_P2);

    cudaFuncSetAttribute(solver_kernel,
                         cudaFuncAttributeMaxDynamicSharedMemorySize, SMEM_BYTES);

    // L1: X1 | Q | P (dual store: plain + interleaved-lower-half)
    precompute_fused<<<dim3(8, 16, 3), 256>>>(b, cin, W1, b1, Aaug, Ainv, X1, Q, P2, Pn);
    // L2: X2 = relu(X1 @ W2 + b2)
    gemm_kernel<<<dim3(8, 16), 256>>>(X1, nullptr, W2, b2, X2, nullptr,
                                      BATCH, HDIM, HDIM, 1, 0, 0);
    // L3: Ys = (X2 @ W3 + b3) / 6
    gemm_kernel<<<dim3(8, 16), 256>>>(X2, nullptr, W3, b3, Ys, nullptr,
                                      BATCH, DTOT, HDIM, 2, 0, 0);
    // L4: C0 = 0.3 Q - 1.8 (Ys @ P)
    gemm_kernel<<<dim3(8, 16), 256>>>(Ys, nullptr, Pn, nullptr, C0, Q,
                                      BATCH, DTOT, DTOT, 5, 0, 0);
    // L5..L8: solver chunks
    for (int ch = 0; ch < NCHUNK; ch++)
        solver_kernel<<<SOLVER_CTAS, NTHR, SMEM_BYTES>>>(out, ch * CHUNK, (ch + 1) * CHUNK);
}